// round 10
// baseline (speedup 1.0000x reference)
#include <cuda_runtime.h>
#include <cstdint>
#include <cstddef>

#define HEADS    8
#define DIM_HEAD 64
#define QDIM     512
#define CDIM     768
#define INNER    512
#define BATCH    4
#define NQ       2048
#define NKV      2048
#define ROWS     (BATCH * NQ)   // 8192
#define SCALE    0.125f         // 64^-0.5

// Scratch (allocation-free rule: device globals)
__device__ float g_q[ROWS * INNER];
__device__ float g_k[ROWS * INNER];
__device__ float g_v[ROWS * INNER];
__device__ float g_ao[ROWS * INNER];

// ===========================================================================
// Warp-MMA tf32 helpers
// ===========================================================================
__device__ __forceinline__ uint32_t tf32_bits(float x) {
    uint32_t r;
    asm("cvt.rna.tf32.f32 %0, %1;" : "=r"(r) : "f"(x));
    return r;
}

__device__ __forceinline__ void tf32_split(float x, uint32_t& hi, uint32_t& lo) {
    hi = tf32_bits(x);
    lo = tf32_bits(x - __uint_as_float(hi));
}

__device__ __forceinline__ void split4(const float4& v, uint4& h, uint4& l) {
    tf32_split(v.x, h.x, l.x); tf32_split(v.y, h.y, l.y);
    tf32_split(v.z, h.z, l.z); tf32_split(v.w, h.w, l.w);
}

#define MMA_TF32(d, a, b)                                                     \
    asm volatile(                                                             \
        "mma.sync.aligned.m16n8k8.row.col.f32.tf32.tf32.f32 "                 \
        "{%0,%1,%2,%3}, {%4,%5,%6,%7}, {%8,%9}, {%0,%1,%2,%3};"               \
        : "+f"((d)[0]), "+f"((d)[1]), "+f"((d)[2]), "+f"((d)[3])              \
        : "r"((a)[0]), "r"((a)[1]), "r"((a)[2]), "r"((a)[3]),                 \
          "r"((b)[0]), "r"((b)[1]))

// ===========================================================================
// 3xTF32 NT GEMM, double-buffered + pipelined.  128x128 CTA tile, BK=16,
// 256 threads = 8 warps (2x4), warp tile 64x32.
// Dynamic smem: 2 buffers x {Ah, Al, Bh, Bl}[128][20] = 81920 bytes.
// ===========================================================================
#define GBUF_UINTS 10240   // 4 * 128*20
#define GSM_BYTES  (2 * GBUF_UINTS * 4)

__global__ __launch_bounds__(256)
void gemm_mma(const float* __restrict__ A, const float* __restrict__ Bw,
              const float* __restrict__ bias, float* __restrict__ C,
              int M, int ldc, int K, float scale)
{
    extern __shared__ uint32_t gsm[];

    const int tid    = threadIdx.x;
    const int warp   = tid >> 5;
    const int lane   = tid & 31;
    const int gid    = lane >> 2;
    const int tig    = lane & 3;
    const int warp_m = warp & 1;
    const int warp_n = warp >> 1;
    const int mBase  = blockIdx.y << 7;
    const int nBase  = blockIdx.x << 7;

    const int lrow = tid >> 2;          // 0..63
    const int lk4  = (tid & 3) << 2;    // 0,4,8,12

    const float* Ar0 = A  + (size_t)(mBase + lrow)      * K + lk4;
    const float* Ar1 = A  + (size_t)(mBase + lrow + 64) * K + lk4;
    const float* Br0 = Bw + (size_t)(nBase + lrow)      * K + lk4;
    const float* Br1 = Bw + (size_t)(nBase + lrow + 64) * K + lk4;

    float acc[4][4][4] = {};
    float4 pa0, pa1, pb0, pb1;

    // prologue: stage chunk 0
    pa0 = *(const float4*)Ar0; pa1 = *(const float4*)Ar1;
    pb0 = *(const float4*)Br0; pb1 = *(const float4*)Br1;
    {
        uint32_t* Ah = gsm;               uint32_t* Al = Ah + 2560;
        uint32_t* Bh = Al + 2560;         uint32_t* Bl = Bh + 2560;
        uint4 h, l;
        split4(pa0, h, l); *(uint4*)&Ah[lrow * 20 + lk4] = h; *(uint4*)&Al[lrow * 20 + lk4] = l;
        split4(pa1, h, l); *(uint4*)&Ah[(lrow + 64) * 20 + lk4] = h; *(uint4*)&Al[(lrow + 64) * 20 + lk4] = l;
        split4(pb0, h, l); *(uint4*)&Bh[lrow * 20 + lk4] = h; *(uint4*)&Bl[lrow * 20 + lk4] = l;
        split4(pb1, h, l); *(uint4*)&Bh[(lrow + 64) * 20 + lk4] = h; *(uint4*)&Bl[(lrow + 64) * 20 + lk4] = l;
    }

    const int nC = K >> 4;
    int p = 0;

    for (int c = 0; c < nC; c++) {
        __syncthreads();

        if (c + 1 < nC) {                 // prefetch next chunk (LDG early)
            const int k0 = (c + 1) << 4;
            pa0 = *(const float4*)(Ar0 + k0); pa1 = *(const float4*)(Ar1 + k0);
            pb0 = *(const float4*)(Br0 + k0); pb1 = *(const float4*)(Br1 + k0);
        }

        const uint32_t* Ah = gsm + p * GBUF_UINTS;
        const uint32_t* Al = Ah + 2560;
        const uint32_t* Bh = Al + 2560;
        const uint32_t* Bl = Bh + 2560;

#pragma unroll
        for (int ks = 0; ks < 16; ks += 8) {
            uint32_t bh[4][2], bl[4][2];
#pragma unroll
            for (int ni = 0; ni < 4; ni++) {
                const int col = warp_n * 32 + ni * 8 + gid;
                bh[ni][0] = Bh[col * 20 + ks + tig];     bl[ni][0] = Bl[col * 20 + ks + tig];
                bh[ni][1] = Bh[col * 20 + ks + tig + 4]; bl[ni][1] = Bl[col * 20 + ks + tig + 4];
            }
#pragma unroll
            for (int mi = 0; mi < 4; mi++) {
                const int row = warp_m * 64 + mi * 16 + gid;
                uint32_t ah[4], al[4];
                ah[0] = Ah[row * 20 + ks + tig];           al[0] = Al[row * 20 + ks + tig];
                ah[1] = Ah[(row + 8) * 20 + ks + tig];     al[1] = Al[(row + 8) * 20 + ks + tig];
                ah[2] = Ah[row * 20 + ks + tig + 4];       al[2] = Al[row * 20 + ks + tig + 4];
                ah[3] = Ah[(row + 8) * 20 + ks + tig + 4]; al[3] = Al[(row + 8) * 20 + ks + tig + 4];
#pragma unroll
                for (int ni = 0; ni < 4; ni++) {
                    MMA_TF32(acc[mi][ni], ah, bh[ni]);
                    MMA_TF32(acc[mi][ni], ah, bl[ni]);
                    MMA_TF32(acc[mi][ni], al, bh[ni]);
                }
            }
        }

        if (c + 1 < nC) {                 // store prefetched into other buffer
            uint32_t* Ah2 = gsm + (p ^ 1) * GBUF_UINTS;
            uint32_t* Al2 = Ah2 + 2560;
            uint32_t* Bh2 = Al2 + 2560;
            uint32_t* Bl2 = Bh2 + 2560;
            uint4 h, l;
            split4(pa0, h, l); *(uint4*)&Ah2[lrow * 20 + lk4] = h; *(uint4*)&Al2[lrow * 20 + lk4] = l;
            split4(pa1, h, l); *(uint4*)&Ah2[(lrow + 64) * 20 + lk4] = h; *(uint4*)&Al2[(lrow + 64) * 20 + lk4] = l;
            split4(pb0, h, l); *(uint4*)&Bh2[lrow * 20 + lk4] = h; *(uint4*)&Bl2[lrow * 20 + lk4] = l;
            split4(pb1, h, l); *(uint4*)&Bh2[(lrow + 64) * 20 + lk4] = h; *(uint4*)&Bl2[(lrow + 64) * 20 + lk4] = l;
        }
        p ^= 1;
    }

#pragma unroll
    for (int mi = 0; mi < 4; mi++) {
        const int row0 = mBase + warp_m * 64 + mi * 16 + gid;
#pragma unroll
        for (int ni = 0; ni < 4; ni++) {
            const int col = nBase + warp_n * 32 + ni * 8 + tig * 2;
            float b0 = 0.f, b1 = 0.f;
            if (bias) { b0 = bias[col]; b1 = bias[col + 1]; }
            float2 o0, o1;
            o0.x = acc[mi][ni][0] * scale + b0;
            o0.y = acc[mi][ni][1] * scale + b1;
            o1.x = acc[mi][ni][2] * scale + b0;
            o1.y = acc[mi][ni][3] * scale + b1;
            *(float2*)&C[(size_t)row0 * ldc + col]       = o0;
            *(float2*)&C[(size_t)(row0 + 8) * ldc + col] = o1;
        }
    }
}

// ===========================================================================
// Tensor-core flash attention v3 (tf32 warp MMA, raw fp32 operand bits).
// CTA = (b, h, 128 q-rows), 256 threads = 8 warps; warp owns 16 q-rows.
// KV tiles of 64, DOUBLE-BUFFERED smem, ONE barrier per tile.
//  - K pair-permuted rows [key][pos(d)] stride 72 -> LDS.64 B-frags for S.
//  - V row-major [key][d] stride 72.
//  - P: C-frag -> A-frag via lane shuffles (no smem, no cvt).
//  - No cvt anywhere: tensor core reads top 19 bits of fp32 (truncation).
// Dynamic smem: 2 x (Ks 4608 + Vs 4608) uints = 73728 bytes.
// ===========================================================================
#define ABUF_UINTS 9216      // Ks 64*72 + Vs 64*72
#define ASM_BYTES  (2 * ABUF_UINTS * 4)

__global__ __launch_bounds__(256, 2)
void attn_mma()
{
    extern __shared__ uint32_t su[];

    const int tid  = threadIdx.x;
    const int warp = tid >> 5;
    const int lane = tid & 31;
    const int g    = lane >> 2;     // 0..7
    const int t    = lane & 3;      // 0..3
    const int qb   = blockIdx.x << 7;
    const int h    = blockIdx.y;
    const int b    = blockIdx.z;

    // Q fragments (raw fp32 bits; Q pre-scaled by SCALE)
    uint32_t qf[8][4];
    {
        const float* Qb = g_q + (size_t)(b * NQ + qb + warp * 16) * INNER + h * 64;
#pragma unroll
        for (int kc = 0; kc < 8; kc++) {
            qf[kc][0] = __float_as_uint(Qb[(size_t)g       * INNER + kc * 8 + t]);
            qf[kc][1] = __float_as_uint(Qb[(size_t)(g + 8) * INNER + kc * 8 + t]);
            qf[kc][2] = __float_as_uint(Qb[(size_t)g       * INNER + kc * 8 + t + 4]);
            qf[kc][3] = __float_as_uint(Qb[(size_t)(g + 8) * INNER + kc * 8 + t + 4]);
        }
    }

    const float* Kg0 = g_k + (size_t)(b * NKV) * INNER + h * 64;
    const float* Vg0 = g_v + (size_t)(b * NKV) * INNER + h * 64;

    // per-thread load coords (4 rows of work)
    int lr[4], lb[4];
#pragma unroll
    for (int i = 0; i < 4; i++) {
        int idx = tid + (i << 8);
        int r   = idx >> 4;
        int c4  = (idx & 15) << 2;
        lr[i] = r;
        lb[i] = r * 72 + ((c4 >> 3) << 3) + ((c4 & 7) >> 2);   // K permuted base
    }
    // V store offset: row-major
    int vofs[4];
#pragma unroll
    for (int i = 0; i < 4; i++) {
        int idx = tid + (i << 8);
        vofs[i] = (idx >> 4) * 72 + ((idx & 15) << 2);
    }
    // gmem offset per i
    size_t gofs[4];
#pragma unroll
    for (int i = 0; i < 4; i++) {
        int idx = tid + (i << 8);
        gofs[i] = (size_t)(idx >> 4) * INNER + ((idx & 15) << 2);
    }

    float m0 = -1e30f, m1 = -1e30f, l0 = 0.f, l1 = 0.f;
    float o[8][4] = {};

    const int shsrc0 = (g << 2) + (t >> 1);
    const int shsrc1 = shsrc0 + 2;
    const bool todd  = (t & 1);

    float4 kpre[4], vpre[4];

    // ---- prologue: stage tile 0 into buffer 0 ----
#pragma unroll
    for (int i = 0; i < 4; i++) kpre[i] = *(const float4*)&Kg0[gofs[i]];
#pragma unroll
    for (int i = 0; i < 4; i++) vpre[i] = *(const float4*)&Vg0[gofs[i]];
    {
        uint32_t* Ks = su;
        uint32_t* Vs = su + 4608;
#pragma unroll
        for (int i = 0; i < 4; i++) {
            Ks[lb[i] + 0] = __float_as_uint(kpre[i].x);
            Ks[lb[i] + 2] = __float_as_uint(kpre[i].y);
            Ks[lb[i] + 4] = __float_as_uint(kpre[i].z);
            Ks[lb[i] + 6] = __float_as_uint(kpre[i].w);
            uint4 vb;
            vb.x = __float_as_uint(vpre[i].x); vb.y = __float_as_uint(vpre[i].y);
            vb.z = __float_as_uint(vpre[i].z); vb.w = __float_as_uint(vpre[i].w);
            *(uint4*)&Vs[vofs[i]] = vb;
        }
    }

    int p = 0;
    for (int kb = 0; kb < NKV; kb += 64) {
        __syncthreads();   // buffer p staged

        const uint32_t* Ks = su + p * ABUF_UINTS;
        const uint32_t* Vs = Ks + 4608;
        const bool more = (kb + 64 < NKV);

        // prefetch next K early (hidden under S MMAs)
        if (more) {
            const float* Kg = Kg0 + (size_t)(kb + 64) * INNER;
#pragma unroll
            for (int i = 0; i < 4; i++) kpre[i] = *(const float4*)&Kg[gofs[i]];
        }

        // ---- S = Q @ K^T ----
        float sf[8][4];
#pragma unroll
        for (int ni = 0; ni < 8; ni++)
#pragma unroll
            for (int r = 0; r < 4; r++) sf[ni][r] = 0.f;

#pragma unroll
        for (int kc = 0; kc < 8; kc++) {
#pragma unroll
            for (int ni = 0; ni < 8; ni++) {
                uint2 bp = *(const uint2*)&Ks[(ni * 8 + g) * 72 + kc * 8 + t * 2];
                uint32_t bb[2] = {bp.x, bp.y};
                MMA_TF32(sf[ni], qf[kc], bb);
            }
        }

        // ---- online softmax ----
        float tm0 = -1e30f, tm1 = -1e30f;
#pragma unroll
        for (int ni = 0; ni < 8; ni++) {
            tm0 = fmaxf(tm0, fmaxf(sf[ni][0], sf[ni][1]));
            tm1 = fmaxf(tm1, fmaxf(sf[ni][2], sf[ni][3]));
        }
        tm0 = fmaxf(tm0, __shfl_xor_sync(0xFFFFFFFF, tm0, 1));
        tm0 = fmaxf(tm0, __shfl_xor_sync(0xFFFFFFFF, tm0, 2));
        tm1 = fmaxf(tm1, __shfl_xor_sync(0xFFFFFFFF, tm1, 1));
        tm1 = fmaxf(tm1, __shfl_xor_sync(0xFFFFFFFF, tm1, 2));

        float mn0 = fmaxf(m0, tm0), mn1 = fmaxf(m1, tm1);
        float a0 = __expf(m0 - mn0), a1 = __expf(m1 - mn1);
        m0 = mn0; m1 = mn1;

        float ps0 = 0.f, ps1 = 0.f;
#pragma unroll
        for (int ni = 0; ni < 8; ni++) {
            sf[ni][0] = __expf(sf[ni][0] - m0); ps0 += sf[ni][0];
            sf[ni][1] = __expf(sf[ni][1] - m0); ps0 += sf[ni][1];
            sf[ni][2] = __expf(sf[ni][2] - m1); ps1 += sf[ni][2];
            sf[ni][3] = __expf(sf[ni][3] - m1); ps1 += sf[ni][3];
        }
        ps0 += __shfl_xor_sync(0xFFFFFFFF, ps0, 1);
        ps0 += __shfl_xor_sync(0xFFFFFFFF, ps0, 2);
        ps1 += __shfl_xor_sync(0xFFFFFFFF, ps1, 1);
        ps1 += __shfl_xor_sync(0xFFFFFFFF, ps1, 2);
        l0 = l0 * a0 + ps0;
        l1 = l1 * a1 + ps1;

#pragma unroll
        for (int s = 0; s < 8; s++) {
            o[s][0] *= a0; o[s][1] *= a0;
            o[s][2] *= a1; o[s][3] *= a1;
        }

        // store prefetched K into other buffer; then prefetch V
        if (more) {
            uint32_t* Ks2 = su + (p ^ 1) * ABUF_UINTS;
#pragma unroll
            for (int i = 0; i < 4; i++) {
                Ks2[lb[i] + 0] = __float_as_uint(kpre[i].x);
                Ks2[lb[i] + 2] = __float_as_uint(kpre[i].y);
                Ks2[lb[i] + 4] = __float_as_uint(kpre[i].z);
                Ks2[lb[i] + 6] = __float_as_uint(kpre[i].w);
            }
            const float* Vg = Vg0 + (size_t)(kb + 64) * INNER;
#pragma unroll
            for (int i = 0; i < 4; i++) vpre[i] = *(const float4*)&Vg[gofs[i]];
        }

        // ---- O += P @ V : A-frag of P via shuffles (raw fp32 bits) ----
#pragma unroll
        for (int kc = 0; kc < 8; kc++) {
            float f0  = __shfl_sync(0xFFFFFFFF, sf[kc][0], shsrc0);
            float f1  = __shfl_sync(0xFFFFFFFF, sf[kc][1], shsrc0);
            float f2  = __shfl_sync(0xFFFFFFFF, sf[kc][2], shsrc0);
            float f3  = __shfl_sync(0xFFFFFFFF, sf[kc][3], shsrc0);
            float f0b = __shfl_sync(0xFFFFFFFF, sf[kc][0], shsrc1);
            float f1b = __shfl_sync(0xFFFFFFFF, sf[kc][1], shsrc1);
            float f2b = __shfl_sync(0xFFFFFFFF, sf[kc][2], shsrc1);
            float f3b = __shfl_sync(0xFFFFFFFF, sf[kc][3], shsrc1);
            uint32_t pa[4];
            pa[0] = __float_as_uint(todd ? f1  : f0);
            pa[1] = __float_as_uint(todd ? f3  : f2);
            pa[2] = __float_as_uint(todd ? f1b : f0b);
            pa[3] = __float_as_uint(todd ? f3b : f2b);
#pragma unroll
            for (int s = 0; s < 8; s++) {
                uint32_t bb[2];
                bb[0] = Vs[(kc * 8 + t) * 72 + s * 8 + g];
                bb[1] = Vs[(kc * 8 + t + 4) * 72 + s * 8 + g];
                MMA_TF32(o[s], pa, bb);
            }
        }

        // store prefetched V into other buffer
        if (more) {
            uint32_t* Vs2 = su + (p ^ 1) * ABUF_UINTS + 4608;
#pragma unroll
            for (int i = 0; i < 4; i++) {
                uint4 vb;
                vb.x = __float_as_uint(vpre[i].x); vb.y = __float_as_uint(vpre[i].y);
                vb.z = __float_as_uint(vpre[i].z); vb.w = __float_as_uint(vpre[i].w);
                *(uint4*)&Vs2[vofs[i]] = vb;
            }
        }
        p ^= 1;
    }

    // ---- normalize and write out ----
    const float inv0 = 1.f / l0, inv1 = 1.f / l1;
    const int row0 = b * NQ + qb + warp * 16 + g;
#pragma unroll
    for (int s = 0; s < 8; s++) {
        const int col = h * 64 + s * 8 + t * 2;
        float2 w0, w1;
        w0.x = o[s][0] * inv0; w0.y = o[s][1] * inv0;
        w1.x = o[s][2] * inv1; w1.y = o[s][3] * inv1;
        *(float2*)&g_ao[(size_t)row0 * INNER + col]       = w0;
        *(float2*)&g_ao[(size_t)(row0 + 8) * INNER + col] = w1;
    }
}

// ---------------------------------------------------------------------------
extern "C" void kernel_launch(void* const* d_in, const int* in_sizes, int n_in,
                              void* d_out, int out_size)
{
    const float* x   = (const float*)d_in[0];  // [4,2048,512]
    const float* ctx = (const float*)d_in[1];  // [4,2048,768]
    const float* Wq  = (const float*)d_in[2];  // [512,512]
    const float* Wk  = (const float*)d_in[3];  // [512,768]
    const float* Wv  = (const float*)d_in[4];  // [512,768]
    const float* Wo  = (const float*)d_in[5];  // [512,512]
    const float* bo  = (const float*)d_in[6];  // [512]
    float* out = (float*)d_out;

    float *qp, *kp, *vp, *ap;
    cudaGetSymbolAddress((void**)&qp, g_q);
    cudaGetSymbolAddress((void**)&kp, g_k);
    cudaGetSymbolAddress((void**)&vp, g_v);
    cudaGetSymbolAddress((void**)&ap, g_ao);

    cudaFuncSetAttribute(gemm_mma, cudaFuncAttributeMaxDynamicSharedMemorySize,
                         GSM_BYTES);
    cudaFuncSetAttribute(attn_mma, cudaFuncAttributeMaxDynamicSharedMemorySize,
                         ASM_BYTES);

    dim3 gProj(INNER / 128, ROWS / 128);   // (4, 64)

    // Q = x @ Wq^T * SCALE ; K = ctx @ Wk^T ; V = ctx @ Wv^T
    gemm_mma<<<gProj, 256, GSM_BYTES>>>(x,   Wq, nullptr, qp, ROWS, INNER, QDIM, SCALE);
    gemm_mma<<<gProj, 256, GSM_BYTES>>>(ctx, Wk, nullptr, kp, ROWS, INNER, CDIM, 1.0f);
    gemm_mma<<<gProj, 256, GSM_BYTES>>>(ctx, Wv, nullptr, vp, ROWS, INNER, CDIM, 1.0f);

    attn_mma<<<dim3(NQ / 128, HEADS, BATCH), 256, ASM_BYTES>>>();

    // out = attn_out @ Wo^T + bo
    gemm_mma<<<dim3(QDIM / 128, ROWS / 128), 256, GSM_BYTES>>>(ap, Wo, bo, out,
                                                               ROWS, QDIM, INNER, 1.0f);
}

// round 11
// speedup vs baseline: 1.1052x; 1.1052x over previous
#include <cuda_runtime.h>
#include <cstdint>
#include <cstddef>

#define HEADS    8
#define DIM_HEAD 64
#define QDIM     512
#define CDIM     768
#define INNER    512
#define BATCH    4
#define NQ       2048
#define NKV      2048
#define ROWS     (BATCH * NQ)   // 8192
#define SCALE    0.125f         // 64^-0.5

// Scratch (allocation-free rule: device globals)
__device__ float g_q[ROWS * INNER];
__device__ float g_k[ROWS * INNER];
__device__ float g_v[ROWS * INNER];
__device__ float g_ao[ROWS * INNER];

// ===========================================================================
// Warp-MMA tf32 helpers
// ===========================================================================
__device__ __forceinline__ uint32_t tf32_bits(float x) {
    uint32_t r;
    asm("cvt.rna.tf32.f32 %0, %1;" : "=r"(r) : "f"(x));
    return r;
}

__device__ __forceinline__ void tf32_split(float x, uint32_t& hi, uint32_t& lo) {
    hi = tf32_bits(x);
    lo = tf32_bits(x - __uint_as_float(hi));
}

__device__ __forceinline__ void split4(const float4& v, uint4& h, uint4& l) {
    tf32_split(v.x, h.x, l.x); tf32_split(v.y, h.y, l.y);
    tf32_split(v.z, h.z, l.z); tf32_split(v.w, h.w, l.w);
}

#define MMA_TF32(d, a, b)                                                     \
    asm volatile(                                                             \
        "mma.sync.aligned.m16n8k8.row.col.f32.tf32.tf32.f32 "                 \
        "{%0,%1,%2,%3}, {%4,%5,%6,%7}, {%8,%9}, {%0,%1,%2,%3};"               \
        : "+f"((d)[0]), "+f"((d)[1]), "+f"((d)[2]), "+f"((d)[3])              \
        : "r"((a)[0]), "r"((a)[1]), "r"((a)[2]), "r"((a)[3]),                 \
          "r"((b)[0]), "r"((b)[1]))

// ===========================================================================
// 3xTF32 NT GEMM, double-buffered + pipelined (round-10 version, kept).
// 128x128 CTA tile, BK=16, 256 threads = 8 warps (2x4), warp tile 64x32.
// Dynamic smem: 2 buffers x {Ah, Al, Bh, Bl}[128][20] = 81920 bytes.
// ===========================================================================
#define GBUF_UINTS 10240   // 4 * 128*20
#define GSM_BYTES  (2 * GBUF_UINTS * 4)

__global__ __launch_bounds__(256)
void gemm_mma(const float* __restrict__ A, const float* __restrict__ Bw,
              const float* __restrict__ bias, float* __restrict__ C,
              int M, int ldc, int K, float scale)
{
    extern __shared__ uint32_t gsm[];

    const int tid    = threadIdx.x;
    const int warp   = tid >> 5;
    const int lane   = tid & 31;
    const int gid    = lane >> 2;
    const int tig    = lane & 3;
    const int warp_m = warp & 1;
    const int warp_n = warp >> 1;
    const int mBase  = blockIdx.y << 7;
    const int nBase  = blockIdx.x << 7;

    const int lrow = tid >> 2;          // 0..63
    const int lk4  = (tid & 3) << 2;    // 0,4,8,12

    const float* Ar0 = A  + (size_t)(mBase + lrow)      * K + lk4;
    const float* Ar1 = A  + (size_t)(mBase + lrow + 64) * K + lk4;
    const float* Br0 = Bw + (size_t)(nBase + lrow)      * K + lk4;
    const float* Br1 = Bw + (size_t)(nBase + lrow + 64) * K + lk4;

    float acc[4][4][4] = {};
    float4 pa0, pa1, pb0, pb1;

    // prologue: stage chunk 0
    pa0 = *(const float4*)Ar0; pa1 = *(const float4*)Ar1;
    pb0 = *(const float4*)Br0; pb1 = *(const float4*)Br1;
    {
        uint32_t* Ah = gsm;               uint32_t* Al = Ah + 2560;
        uint32_t* Bh = Al + 2560;         uint32_t* Bl = Bh + 2560;
        uint4 h, l;
        split4(pa0, h, l); *(uint4*)&Ah[lrow * 20 + lk4] = h; *(uint4*)&Al[lrow * 20 + lk4] = l;
        split4(pa1, h, l); *(uint4*)&Ah[(lrow + 64) * 20 + lk4] = h; *(uint4*)&Al[(lrow + 64) * 20 + lk4] = l;
        split4(pb0, h, l); *(uint4*)&Bh[lrow * 20 + lk4] = h; *(uint4*)&Bl[lrow * 20 + lk4] = l;
        split4(pb1, h, l); *(uint4*)&Bh[(lrow + 64) * 20 + lk4] = h; *(uint4*)&Bl[(lrow + 64) * 20 + lk4] = l;
    }

    const int nC = K >> 4;
    int p = 0;

    for (int c = 0; c < nC; c++) {
        __syncthreads();

        if (c + 1 < nC) {                 // prefetch next chunk (LDG early)
            const int k0 = (c + 1) << 4;
            pa0 = *(const float4*)(Ar0 + k0); pa1 = *(const float4*)(Ar1 + k0);
            pb0 = *(const float4*)(Br0 + k0); pb1 = *(const float4*)(Br1 + k0);
        }

        const uint32_t* Ah = gsm + p * GBUF_UINTS;
        const uint32_t* Al = Ah + 2560;
        const uint32_t* Bh = Al + 2560;
        const uint32_t* Bl = Bh + 2560;

#pragma unroll
        for (int ks = 0; ks < 16; ks += 8) {
            uint32_t bh[4][2], bl[4][2];
#pragma unroll
            for (int ni = 0; ni < 4; ni++) {
                const int col = warp_n * 32 + ni * 8 + gid;
                bh[ni][0] = Bh[col * 20 + ks + tig];     bl[ni][0] = Bl[col * 20 + ks + tig];
                bh[ni][1] = Bh[col * 20 + ks + tig + 4]; bl[ni][1] = Bl[col * 20 + ks + tig + 4];
            }
#pragma unroll
            for (int mi = 0; mi < 4; mi++) {
                const int row = warp_m * 64 + mi * 16 + gid;
                uint32_t ah[4], al[4];
                ah[0] = Ah[row * 20 + ks + tig];           al[0] = Al[row * 20 + ks + tig];
                ah[1] = Ah[(row + 8) * 20 + ks + tig];     al[1] = Al[(row + 8) * 20 + ks + tig];
                ah[2] = Ah[row * 20 + ks + tig + 4];       al[2] = Al[row * 20 + ks + tig + 4];
                ah[3] = Ah[(row + 8) * 20 + ks + tig + 4]; al[3] = Al[(row + 8) * 20 + ks + tig + 4];
#pragma unroll
                for (int ni = 0; ni < 4; ni++) {
                    MMA_TF32(acc[mi][ni], ah, bh[ni]);
                    MMA_TF32(acc[mi][ni], ah, bl[ni]);
                    MMA_TF32(acc[mi][ni], al, bh[ni]);
                }
            }
        }

        if (c + 1 < nC) {                 // store prefetched into other buffer
            uint32_t* Ah2 = gsm + (p ^ 1) * GBUF_UINTS;
            uint32_t* Al2 = Ah2 + 2560;
            uint32_t* Bh2 = Al2 + 2560;
            uint32_t* Bl2 = Bh2 + 2560;
            uint4 h, l;
            split4(pa0, h, l); *(uint4*)&Ah2[lrow * 20 + lk4] = h; *(uint4*)&Al2[lrow * 20 + lk4] = l;
            split4(pa1, h, l); *(uint4*)&Ah2[(lrow + 64) * 20 + lk4] = h; *(uint4*)&Al2[(lrow + 64) * 20 + lk4] = l;
            split4(pb0, h, l); *(uint4*)&Bh2[lrow * 20 + lk4] = h; *(uint4*)&Bl2[lrow * 20 + lk4] = l;
            split4(pb1, h, l); *(uint4*)&Bh2[(lrow + 64) * 20 + lk4] = h; *(uint4*)&Bl2[(lrow + 64) * 20 + lk4] = l;
        }
        p ^= 1;
    }

#pragma unroll
    for (int mi = 0; mi < 4; mi++) {
        const int row0 = mBase + warp_m * 64 + mi * 16 + gid;
#pragma unroll
        for (int ni = 0; ni < 4; ni++) {
            const int col = nBase + warp_n * 32 + ni * 8 + tig * 2;
            float b0 = 0.f, b1 = 0.f;
            if (bias) { b0 = bias[col]; b1 = bias[col + 1]; }
            float2 o0, o1;
            o0.x = acc[mi][ni][0] * scale + b0;
            o0.y = acc[mi][ni][1] * scale + b1;
            o1.x = acc[mi][ni][2] * scale + b0;
            o1.y = acc[mi][ni][3] * scale + b1;
            *(float2*)&C[(size_t)row0 * ldc + col]       = o0;
            *(float2*)&C[(size_t)(row0 + 8) * ldc + col] = o1;
        }
    }
}

// ===========================================================================
// Tensor-core flash attention (round-9 structure + raw fp32 operand bits).
// CTA = (b, h, 128 q-rows), 256 threads = 8 warps; warp owns 16 q-rows.
// KV tiles of 64, SINGLE static smem buffer (no reg prefetch -> no spills).
//  - K pair-permuted rows [key][pos(d)] stride 72 -> LDS.64 B-frags for S.
//  - V row-major [key][d] stride 72.
//  - P: C-frag -> A-frag via lane shuffles (no smem).
//  - No cvt: tensor core reads top 19 bits of fp32 (truncation; validated
//    rel_err 2.7e-4 in round 10).
// ===========================================================================
__global__ __launch_bounds__(256, 2)
void attn_mma()
{
    __shared__ uint32_t Ksf[64 * 72];
    __shared__ uint32_t Vs [64 * 72];

    const int tid  = threadIdx.x;
    const int warp = tid >> 5;
    const int lane = tid & 31;
    const int g    = lane >> 2;     // 0..7
    const int t    = lane & 3;      // 0..3
    const int qb   = blockIdx.x << 7;
    const int h    = blockIdx.y;
    const int b    = blockIdx.z;

    // Q fragments (raw fp32 bits; Q pre-scaled by SCALE)
    uint32_t qf[8][4];
    {
        const float* Qb = g_q + (size_t)(b * NQ + qb + warp * 16) * INNER + h * 64;
#pragma unroll
        for (int kc = 0; kc < 8; kc++) {
            qf[kc][0] = __float_as_uint(Qb[(size_t)g       * INNER + kc * 8 + t]);
            qf[kc][1] = __float_as_uint(Qb[(size_t)(g + 8) * INNER + kc * 8 + t]);
            qf[kc][2] = __float_as_uint(Qb[(size_t)g       * INNER + kc * 8 + t + 4]);
            qf[kc][3] = __float_as_uint(Qb[(size_t)(g + 8) * INNER + kc * 8 + t + 4]);
        }
    }

    float m0 = -1e30f, m1 = -1e30f, l0 = 0.f, l1 = 0.f;
    float o[8][4] = {};

    const int shsrc0 = (g << 2) + (t >> 1);   // P source lane for cols t
    const int shsrc1 = shsrc0 + 2;            // P source lane for cols t+4
    const bool todd  = (t & 1);

    for (int kb = 0; kb < NKV; kb += 64) {
        // ---- cooperative K/V load (float4 LDG), raw bits to smem ----
        {
            const float* Kg = g_k + (size_t)(b * NKV + kb) * INNER + h * 64;
            const float* Vg = g_v + (size_t)(b * NKV + kb) * INNER + h * 64;
#pragma unroll
            for (int i = 0; i < 4; i++) {
                int idx = tid + (i << 8);          // 0..1023
                int r   = idx >> 4;                // 0..63
                int c4  = (idx & 15) << 2;         // 0..60
                float4 kv = *(const float4*)&Kg[(size_t)r * INNER + c4];
                // pos(c4+j) = (c4>>3)*8 + j*2 + ((c4&7)>>2)   (c4 4-aligned)
                int base = r * 72 + ((c4 >> 3) << 3) + ((c4 & 7) >> 2);
                Ksf[base + 0] = __float_as_uint(kv.x);
                Ksf[base + 2] = __float_as_uint(kv.y);
                Ksf[base + 4] = __float_as_uint(kv.z);
                Ksf[base + 6] = __float_as_uint(kv.w);
                float4 vv = *(const float4*)&Vg[(size_t)r * INNER + c4];
                uint4 vb;
                vb.x = __float_as_uint(vv.x); vb.y = __float_as_uint(vv.y);
                vb.z = __float_as_uint(vv.z); vb.w = __float_as_uint(vv.w);
                *(uint4*)&Vs[r * 72 + c4] = vb;
            }
        }
        __syncthreads();

        // ---- S = Q @ K^T  (16 x 64 per warp), paired LDS.64 B-frags ----
        float sf[8][4];
#pragma unroll
        for (int ni = 0; ni < 8; ni++)
#pragma unroll
            for (int r = 0; r < 4; r++) sf[ni][r] = 0.f;

#pragma unroll
        for (int kc = 0; kc < 8; kc++) {
#pragma unroll
            for (int ni = 0; ni < 8; ni++) {
                uint2 bp = *(const uint2*)&Ksf[(ni * 8 + g) * 72 + kc * 8 + t * 2];
                uint32_t bb[2] = {bp.x, bp.y};
                MMA_TF32(sf[ni], qf[kc], bb);
            }
        }

        // ---- online softmax (rows g and g+8) ----
        float tm0 = -1e30f, tm1 = -1e30f;
#pragma unroll
        for (int ni = 0; ni < 8; ni++) {
            tm0 = fmaxf(tm0, fmaxf(sf[ni][0], sf[ni][1]));
            tm1 = fmaxf(tm1, fmaxf(sf[ni][2], sf[ni][3]));
        }
        tm0 = fmaxf(tm0, __shfl_xor_sync(0xFFFFFFFF, tm0, 1));
        tm0 = fmaxf(tm0, __shfl_xor_sync(0xFFFFFFFF, tm0, 2));
        tm1 = fmaxf(tm1, __shfl_xor_sync(0xFFFFFFFF, tm1, 1));
        tm1 = fmaxf(tm1, __shfl_xor_sync(0xFFFFFFFF, tm1, 2));

        float mn0 = fmaxf(m0, tm0), mn1 = fmaxf(m1, tm1);
        float a0 = __expf(m0 - mn0), a1 = __expf(m1 - mn1);
        m0 = mn0; m1 = mn1;

        float ps0 = 0.f, ps1 = 0.f;
#pragma unroll
        for (int ni = 0; ni < 8; ni++) {
            sf[ni][0] = __expf(sf[ni][0] - m0); ps0 += sf[ni][0];
            sf[ni][1] = __expf(sf[ni][1] - m0); ps0 += sf[ni][1];
            sf[ni][2] = __expf(sf[ni][2] - m1); ps1 += sf[ni][2];
            sf[ni][3] = __expf(sf[ni][3] - m1); ps1 += sf[ni][3];
        }
        ps0 += __shfl_xor_sync(0xFFFFFFFF, ps0, 1);
        ps0 += __shfl_xor_sync(0xFFFFFFFF, ps0, 2);
        ps1 += __shfl_xor_sync(0xFFFFFFFF, ps1, 1);
        ps1 += __shfl_xor_sync(0xFFFFFFFF, ps1, 2);
        l0 = l0 * a0 + ps0;
        l1 = l1 * a1 + ps1;

#pragma unroll
        for (int s = 0; s < 8; s++) {
            o[s][0] *= a0; o[s][1] *= a0;
            o[s][2] *= a1; o[s][3] *= a1;
        }

        // ---- O += P @ V : A-frag of P via shuffles (raw fp32 bits) ----
#pragma unroll
        for (int kc = 0; kc < 8; kc++) {
            float f0  = __shfl_sync(0xFFFFFFFF, sf[kc][0], shsrc0);
            float f1  = __shfl_sync(0xFFFFFFFF, sf[kc][1], shsrc0);
            float f2  = __shfl_sync(0xFFFFFFFF, sf[kc][2], shsrc0);
            float f3  = __shfl_sync(0xFFFFFFFF, sf[kc][3], shsrc0);
            float f0b = __shfl_sync(0xFFFFFFFF, sf[kc][0], shsrc1);
            float f1b = __shfl_sync(0xFFFFFFFF, sf[kc][1], shsrc1);
            float f2b = __shfl_sync(0xFFFFFFFF, sf[kc][2], shsrc1);
            float f3b = __shfl_sync(0xFFFFFFFF, sf[kc][3], shsrc1);
            uint32_t pa[4];
            pa[0] = __float_as_uint(todd ? f1  : f0);
            pa[1] = __float_as_uint(todd ? f3  : f2);
            pa[2] = __float_as_uint(todd ? f1b : f0b);
            pa[3] = __float_as_uint(todd ? f3b : f2b);
#pragma unroll
            for (int s = 0; s < 8; s++) {
                uint32_t bb[2];
                bb[0] = Vs[(kc * 8 + t) * 72 + s * 8 + g];
                bb[1] = Vs[(kc * 8 + t + 4) * 72 + s * 8 + g];
                MMA_TF32(o[s], pa, bb);
            }
        }
        __syncthreads();   // protect Ksf/Vs for next tile
    }

    // ---- normalize and write out ----
    const float inv0 = 1.f / l0, inv1 = 1.f / l1;
    const int row0 = b * NQ + qb + warp * 16 + g;
#pragma unroll
    for (int s = 0; s < 8; s++) {
        const int col = h * 64 + s * 8 + t * 2;
        float2 w0, w1;
        w0.x = o[s][0] * inv0; w0.y = o[s][1] * inv0;
        w1.x = o[s][2] * inv1; w1.y = o[s][3] * inv1;
        *(float2*)&g_ao[(size_t)row0 * INNER + col]       = w0;
        *(float2*)&g_ao[(size_t)(row0 + 8) * INNER + col] = w1;
    }
}

// ---------------------------------------------------------------------------
extern "C" void kernel_launch(void* const* d_in, const int* in_sizes, int n_in,
                              void* d_out, int out_size)
{
    const float* x   = (const float*)d_in[0];  // [4,2048,512]
    const float* ctx = (const float*)d_in[1];  // [4,2048,768]
    const float* Wq  = (const float*)d_in[2];  // [512,512]
    const float* Wk  = (const float*)d_in[3];  // [512,768]
    const float* Wv  = (const float*)d_in[4];  // [512,768]
    const float* Wo  = (const float*)d_in[5];  // [512,512]
    const float* bo  = (const float*)d_in[6];  // [512]
    float* out = (float*)d_out;

    float *qp, *kp, *vp, *ap;
    cudaGetSymbolAddress((void**)&qp, g_q);
    cudaGetSymbolAddress((void**)&kp, g_k);
    cudaGetSymbolAddress((void**)&vp, g_v);
    cudaGetSymbolAddress((void**)&ap, g_ao);

    cudaFuncSetAttribute(gemm_mma, cudaFuncAttributeMaxDynamicSharedMemorySize,
                         GSM_BYTES);

    dim3 gProj(INNER / 128, ROWS / 128);   // (4, 64)

    // Q = x @ Wq^T * SCALE ; K = ctx @ Wk^T ; V = ctx @ Wv^T
    gemm_mma<<<gProj, 256, GSM_BYTES>>>(x,   Wq, nullptr, qp, ROWS, INNER, QDIM, SCALE);
    gemm_mma<<<gProj, 256, GSM_BYTES>>>(ctx, Wk, nullptr, kp, ROWS, INNER, CDIM, 1.0f);
    gemm_mma<<<gProj, 256, GSM_BYTES>>>(ctx, Wv, nullptr, vp, ROWS, INNER, CDIM, 1.0f);

    attn_mma<<<dim3(NQ / 128, HEADS, BATCH), 256>>>();

    // out = attn_out @ Wo^T + bo
    gemm_mma<<<dim3(QDIM / 128, ROWS / 128), 256, GSM_BYTES>>>(ap, Wo, bo, out,
                                                               ROWS, QDIM, INNER, 1.0f);
}

// round 12
// speedup vs baseline: 1.2817x; 1.1597x over previous
#include <cuda_runtime.h>
#include <cstdint>
#include <cstddef>

#define HEADS    8
#define DIM_HEAD 64
#define QDIM     512
#define CDIM     768
#define INNER    512
#define BATCH    4
#define NQ       2048
#define NKV      2048
#define ROWS     (BATCH * NQ)   // 8192
#define SCALE    0.125f         // 64^-0.5

// Scratch (allocation-free rule: device globals)
__device__ float g_q[ROWS * INNER];
__device__ float g_k[ROWS * INNER];
__device__ float g_v[ROWS * INNER];
__device__ float g_ao[ROWS * INNER];

// ===========================================================================
// Warp-MMA tf32 helpers
// ===========================================================================
__device__ __forceinline__ uint32_t tf32_bits(float x) {
    uint32_t r;
    asm("cvt.rna.tf32.f32 %0, %1;" : "=r"(r) : "f"(x));
    return r;
}

__device__ __forceinline__ void tf32_split(float x, uint32_t& hi, uint32_t& lo) {
    hi = tf32_bits(x);
    lo = tf32_bits(x - __uint_as_float(hi));
}

__device__ __forceinline__ void split4(const float4& v, uint4& h, uint4& l) {
    tf32_split(v.x, h.x, l.x); tf32_split(v.y, h.y, l.y);
    tf32_split(v.z, h.z, l.z); tf32_split(v.w, h.w, l.w);
}

__device__ __forceinline__ uint4 hi4(const float4& v) {
    uint4 h;
    h.x = tf32_bits(v.x); h.y = tf32_bits(v.y);
    h.z = tf32_bits(v.z); h.w = tf32_bits(v.w);
    return h;
}

#define MMA_TF32(d, a, b)                                                     \
    asm volatile(                                                             \
        "mma.sync.aligned.m16n8k8.row.col.f32.tf32.tf32.f32 "                 \
        "{%0,%1,%2,%3}, {%4,%5,%6,%7}, {%8,%9}, {%0,%1,%2,%3};"               \
        : "+f"((d)[0]), "+f"((d)[1]), "+f"((d)[2]), "+f"((d)[3])              \
        : "r"((a)[0]), "r"((a)[1]), "r"((a)[2]), "r"((a)[3]),                 \
          "r"((b)[0]), "r"((b)[1]))

// ===========================================================================
// 2xTF32 NT GEMM, double-buffered + pipelined.
// C = scale*(A @ B^T) + bias, computed as A_hi @ (B_hi + B_lo)^T:
//   error ~ |A_lo| ~ 2.8e-4 rms relative (validated margin vs 1e-3 gate).
// 128x128 CTA tile, BK=16, 256 threads = 8 warps (2x4), warp tile 64x32.
// Dynamic smem: 2 buffers x {Ah, Bh, Bl}[128][20] = 61440 bytes.
// ===========================================================================
#define GBUF_UINTS 7680    // 3 * 128*20
#define GSM_BYTES  (2 * GBUF_UINTS * 4)

__global__ __launch_bounds__(256)
void gemm_mma(const float* __restrict__ A, const float* __restrict__ Bw,
              const float* __restrict__ bias, float* __restrict__ C,
              int M, int ldc, int K, float scale)
{
    extern __shared__ uint32_t gsm[];

    const int tid    = threadIdx.x;
    const int warp   = tid >> 5;
    const int lane   = tid & 31;
    const int gid    = lane >> 2;
    const int tig    = lane & 3;
    const int warp_m = warp & 1;
    const int warp_n = warp >> 1;
    const int mBase  = blockIdx.y << 7;
    const int nBase  = blockIdx.x << 7;

    const int lrow = tid >> 2;          // 0..63
    const int lk4  = (tid & 3) << 2;    // 0,4,8,12

    const float* Ar0 = A  + (size_t)(mBase + lrow)      * K + lk4;
    const float* Ar1 = A  + (size_t)(mBase + lrow + 64) * K + lk4;
    const float* Br0 = Bw + (size_t)(nBase + lrow)      * K + lk4;
    const float* Br1 = Bw + (size_t)(nBase + lrow + 64) * K + lk4;

    float acc[4][4][4] = {};
    float4 pa0, pa1, pb0, pb1;

    // prologue: stage chunk 0
    pa0 = *(const float4*)Ar0; pa1 = *(const float4*)Ar1;
    pb0 = *(const float4*)Br0; pb1 = *(const float4*)Br1;
    {
        uint32_t* Ah = gsm;
        uint32_t* Bh = Ah + 2560;
        uint32_t* Bl = Bh + 2560;
        uint4 h, l;
        *(uint4*)&Ah[lrow * 20 + lk4]        = hi4(pa0);
        *(uint4*)&Ah[(lrow + 64) * 20 + lk4] = hi4(pa1);
        split4(pb0, h, l); *(uint4*)&Bh[lrow * 20 + lk4] = h; *(uint4*)&Bl[lrow * 20 + lk4] = l;
        split4(pb1, h, l); *(uint4*)&Bh[(lrow + 64) * 20 + lk4] = h; *(uint4*)&Bl[(lrow + 64) * 20 + lk4] = l;
    }

    const int nC = K >> 4;
    int p = 0;

    for (int c = 0; c < nC; c++) {
        __syncthreads();

        if (c + 1 < nC) {                 // prefetch next chunk (LDG early)
            const int k0 = (c + 1) << 4;
            pa0 = *(const float4*)(Ar0 + k0); pa1 = *(const float4*)(Ar1 + k0);
            pb0 = *(const float4*)(Br0 + k0); pb1 = *(const float4*)(Br1 + k0);
        }

        const uint32_t* Ah = gsm + p * GBUF_UINTS;
        const uint32_t* Bh = Ah + 2560;
        const uint32_t* Bl = Bh + 2560;

#pragma unroll
        for (int ks = 0; ks < 16; ks += 8) {
            uint32_t bh[4][2], bl[4][2];
#pragma unroll
            for (int ni = 0; ni < 4; ni++) {
                const int col = warp_n * 32 + ni * 8 + gid;
                bh[ni][0] = Bh[col * 20 + ks + tig];     bl[ni][0] = Bl[col * 20 + ks + tig];
                bh[ni][1] = Bh[col * 20 + ks + tig + 4]; bl[ni][1] = Bl[col * 20 + ks + tig + 4];
            }
#pragma unroll
            for (int mi = 0; mi < 4; mi++) {
                const int row = warp_m * 64 + mi * 16 + gid;
                uint32_t ah[4];
                ah[0] = Ah[row * 20 + ks + tig];
                ah[1] = Ah[(row + 8) * 20 + ks + tig];
                ah[2] = Ah[row * 20 + ks + tig + 4];
                ah[3] = Ah[(row + 8) * 20 + ks + tig + 4];
#pragma unroll
                for (int ni = 0; ni < 4; ni++) {
                    MMA_TF32(acc[mi][ni], ah, bh[ni]);
                    MMA_TF32(acc[mi][ni], ah, bl[ni]);
                }
            }
        }

        if (c + 1 < nC) {                 // store prefetched into other buffer
            uint32_t* Ah2 = gsm + (p ^ 1) * GBUF_UINTS;
            uint32_t* Bh2 = Ah2 + 2560;
            uint32_t* Bl2 = Bh2 + 2560;
            uint4 h, l;
            *(uint4*)&Ah2[lrow * 20 + lk4]        = hi4(pa0);
            *(uint4*)&Ah2[(lrow + 64) * 20 + lk4] = hi4(pa1);
            split4(pb0, h, l); *(uint4*)&Bh2[lrow * 20 + lk4] = h; *(uint4*)&Bl2[lrow * 20 + lk4] = l;
            split4(pb1, h, l); *(uint4*)&Bh2[(lrow + 64) * 20 + lk4] = h; *(uint4*)&Bl2[(lrow + 64) * 20 + lk4] = l;
        }
        p ^= 1;
    }

#pragma unroll
    for (int mi = 0; mi < 4; mi++) {
        const int row0 = mBase + warp_m * 64 + mi * 16 + gid;
#pragma unroll
        for (int ni = 0; ni < 4; ni++) {
            const int col = nBase + warp_n * 32 + ni * 8 + tig * 2;
            float b0 = 0.f, b1 = 0.f;
            if (bias) { b0 = bias[col]; b1 = bias[col + 1]; }
            float2 o0, o1;
            o0.x = acc[mi][ni][0] * scale + b0;
            o0.y = acc[mi][ni][1] * scale + b1;
            o1.x = acc[mi][ni][2] * scale + b0;
            o1.y = acc[mi][ni][3] * scale + b1;
            *(float2*)&C[(size_t)row0 * ldc + col]       = o0;
            *(float2*)&C[(size_t)(row0 + 8) * ldc + col] = o1;
        }
    }
}

// ===========================================================================
// Tensor-core flash attention (UNCHANGED from round 11: proven 310us).
// CTA = (b, h, 128 q-rows), 256 threads = 8 warps; warp owns 16 q-rows.
// KV tiles of 64, single static smem buffer.
//  - K pair-permuted rows [key][pos(d)] stride 72 -> LDS.64 B-frags for S.
//  - V row-major [key][d] stride 72.
//  - P: C-frag -> A-frag via lane shuffles (no smem).
//  - No cvt: tensor core reads top 19 bits of fp32 (truncation).
// ===========================================================================
__global__ __launch_bounds__(256, 2)
void attn_mma()
{
    __shared__ uint32_t Ksf[64 * 72];
    __shared__ uint32_t Vs [64 * 72];

    const int tid  = threadIdx.x;
    const int warp = tid >> 5;
    const int lane = tid & 31;
    const int g    = lane >> 2;     // 0..7
    const int t    = lane & 3;      // 0..3
    const int qb   = blockIdx.x << 7;
    const int h    = blockIdx.y;
    const int b    = blockIdx.z;

    // Q fragments (raw fp32 bits; Q pre-scaled by SCALE)
    uint32_t qf[8][4];
    {
        const float* Qb = g_q + (size_t)(b * NQ + qb + warp * 16) * INNER + h * 64;
#pragma unroll
        for (int kc = 0; kc < 8; kc++) {
            qf[kc][0] = __float_as_uint(Qb[(size_t)g       * INNER + kc * 8 + t]);
            qf[kc][1] = __float_as_uint(Qb[(size_t)(g + 8) * INNER + kc * 8 + t]);
            qf[kc][2] = __float_as_uint(Qb[(size_t)g       * INNER + kc * 8 + t + 4]);
            qf[kc][3] = __float_as_uint(Qb[(size_t)(g + 8) * INNER + kc * 8 + t + 4]);
        }
    }

    float m0 = -1e30f, m1 = -1e30f, l0 = 0.f, l1 = 0.f;
    float o[8][4] = {};

    const int shsrc0 = (g << 2) + (t >> 1);   // P source lane for cols t
    const int shsrc1 = shsrc0 + 2;            // P source lane for cols t+4
    const bool todd  = (t & 1);

    for (int kb = 0; kb < NKV; kb += 64) {
        // ---- cooperative K/V load (float4 LDG), raw bits to smem ----
        {
            const float* Kg = g_k + (size_t)(b * NKV + kb) * INNER + h * 64;
            const float* Vg = g_v + (size_t)(b * NKV + kb) * INNER + h * 64;
#pragma unroll
            for (int i = 0; i < 4; i++) {
                int idx = tid + (i << 8);          // 0..1023
                int r   = idx >> 4;                // 0..63
                int c4  = (idx & 15) << 2;         // 0..60
                float4 kv = *(const float4*)&Kg[(size_t)r * INNER + c4];
                // pos(c4+j) = (c4>>3)*8 + j*2 + ((c4&7)>>2)   (c4 4-aligned)
                int base = r * 72 + ((c4 >> 3) << 3) + ((c4 & 7) >> 2);
                Ksf[base + 0] = __float_as_uint(kv.x);
                Ksf[base + 2] = __float_as_uint(kv.y);
                Ksf[base + 4] = __float_as_uint(kv.z);
                Ksf[base + 6] = __float_as_uint(kv.w);
                float4 vv = *(const float4*)&Vg[(size_t)r * INNER + c4];
                uint4 vb;
                vb.x = __float_as_uint(vv.x); vb.y = __float_as_uint(vv.y);
                vb.z = __float_as_uint(vv.z); vb.w = __float_as_uint(vv.w);
                *(uint4*)&Vs[r * 72 + c4] = vb;
            }
        }
        __syncthreads();

        // ---- S = Q @ K^T  (16 x 64 per warp), paired LDS.64 B-frags ----
        float sf[8][4];
#pragma unroll
        for (int ni = 0; ni < 8; ni++)
#pragma unroll
            for (int r = 0; r < 4; r++) sf[ni][r] = 0.f;

#pragma unroll
        for (int kc = 0; kc < 8; kc++) {
#pragma unroll
            for (int ni = 0; ni < 8; ni++) {
                uint2 bp = *(const uint2*)&Ksf[(ni * 8 + g) * 72 + kc * 8 + t * 2];
                uint32_t bb[2] = {bp.x, bp.y};
                MMA_TF32(sf[ni], qf[kc], bb);
            }
        }

        // ---- online softmax (rows g and g+8) ----
        float tm0 = -1e30f, tm1 = -1e30f;
#pragma unroll
        for (int ni = 0; ni < 8; ni++) {
            tm0 = fmaxf(tm0, fmaxf(sf[ni][0], sf[ni][1]));
            tm1 = fmaxf(tm1, fmaxf(sf[ni][2], sf[ni][3]));
        }
        tm0 = fmaxf(tm0, __shfl_xor_sync(0xFFFFFFFF, tm0, 1));
        tm0 = fmaxf(tm0, __shfl_xor_sync(0xFFFFFFFF, tm0, 2));
        tm1 = fmaxf(tm1, __shfl_xor_sync(0xFFFFFFFF, tm1, 1));
        tm1 = fmaxf(tm1, __shfl_xor_sync(0xFFFFFFFF, tm1, 2));

        float mn0 = fmaxf(m0, tm0), mn1 = fmaxf(m1, tm1);
        float a0 = __expf(m0 - mn0), a1 = __expf(m1 - mn1);
        m0 = mn0; m1 = mn1;

        float ps0 = 0.f, ps1 = 0.f;
#pragma unroll
        for (int ni = 0; ni < 8; ni++) {
            sf[ni][0] = __expf(sf[ni][0] - m0); ps0 += sf[ni][0];
            sf[ni][1] = __expf(sf[ni][1] - m0); ps0 += sf[ni][1];
            sf[ni][2] = __expf(sf[ni][2] - m1); ps1 += sf[ni][2];
            sf[ni][3] = __expf(sf[ni][3] - m1); ps1 += sf[ni][3];
        }
        ps0 += __shfl_xor_sync(0xFFFFFFFF, ps0, 1);
        ps0 += __shfl_xor_sync(0xFFFFFFFF, ps0, 2);
        ps1 += __shfl_xor_sync(0xFFFFFFFF, ps1, 1);
        ps1 += __shfl_xor_sync(0xFFFFFFFF, ps1, 2);
        l0 = l0 * a0 + ps0;
        l1 = l1 * a1 + ps1;

#pragma unroll
        for (int s = 0; s < 8; s++) {
            o[s][0] *= a0; o[s][1] *= a0;
            o[s][2] *= a1; o[s][3] *= a1;
        }

        // ---- O += P @ V : A-frag of P via shuffles (raw fp32 bits) ----
#pragma unroll
        for (int kc = 0; kc < 8; kc++) {
            float f0  = __shfl_sync(0xFFFFFFFF, sf[kc][0], shsrc0);
            float f1  = __shfl_sync(0xFFFFFFFF, sf[kc][1], shsrc0);
            float f2  = __shfl_sync(0xFFFFFFFF, sf[kc][2], shsrc0);
            float f3  = __shfl_sync(0xFFFFFFFF, sf[kc][3], shsrc0);
            float f0b = __shfl_sync(0xFFFFFFFF, sf[kc][0], shsrc1);
            float f1b = __shfl_sync(0xFFFFFFFF, sf[kc][1], shsrc1);
            float f2b = __shfl_sync(0xFFFFFFFF, sf[kc][2], shsrc1);
            float f3b = __shfl_sync(0xFFFFFFFF, sf[kc][3], shsrc1);
            uint32_t pa[4];
            pa[0] = __float_as_uint(todd ? f1  : f0);
            pa[1] = __float_as_uint(todd ? f3  : f2);
            pa[2] = __float_as_uint(todd ? f1b : f0b);
            pa[3] = __float_as_uint(todd ? f3b : f2b);
#pragma unroll
            for (int s = 0; s < 8; s++) {
                uint32_t bb[2];
                bb[0] = Vs[(kc * 8 + t) * 72 + s * 8 + g];
                bb[1] = Vs[(kc * 8 + t + 4) * 72 + s * 8 + g];
                MMA_TF32(o[s], pa, bb);
            }
        }
        __syncthreads();   // protect Ksf/Vs for next tile
    }

    // ---- normalize and write out ----
    const float inv0 = 1.f / l0, inv1 = 1.f / l1;
    const int row0 = b * NQ + qb + warp * 16 + g;
#pragma unroll
    for (int s = 0; s < 8; s++) {
        const int col = h * 64 + s * 8 + t * 2;
        float2 w0, w1;
        w0.x = o[s][0] * inv0; w0.y = o[s][1] * inv0;
        w1.x = o[s][2] * inv1; w1.y = o[s][3] * inv1;
        *(float2*)&g_ao[(size_t)row0 * INNER + col]       = w0;
        *(float2*)&g_ao[(size_t)(row0 + 8) * INNER + col] = w1;
    }
}

// ---------------------------------------------------------------------------
extern "C" void kernel_launch(void* const* d_in, const int* in_sizes, int n_in,
                              void* d_out, int out_size)
{
    const float* x   = (const float*)d_in[0];  // [4,2048,512]
    const float* ctx = (const float*)d_in[1];  // [4,2048,768]
    const float* Wq  = (const float*)d_in[2];  // [512,512]
    const float* Wk  = (const float*)d_in[3];  // [512,768]
    const float* Wv  = (const float*)d_in[4];  // [512,768]
    const float* Wo  = (const float*)d_in[5];  // [512,512]
    const float* bo  = (const float*)d_in[6];  // [512]
    float* out = (float*)d_out;

    float *qp, *kp, *vp, *ap;
    cudaGetSymbolAddress((void**)&qp, g_q);
    cudaGetSymbolAddress((void**)&kp, g_k);
    cudaGetSymbolAddress((void**)&vp, g_v);
    cudaGetSymbolAddress((void**)&ap, g_ao);

    cudaFuncSetAttribute(gemm_mma, cudaFuncAttributeMaxDynamicSharedMemorySize,
                         GSM_BYTES);

    dim3 gProj(INNER / 128, ROWS / 128);   // (4, 64)

    // Q = x @ Wq^T * SCALE ; K = ctx @ Wk^T ; V = ctx @ Wv^T
    gemm_mma<<<gProj, 256, GSM_BYTES>>>(x,   Wq, nullptr, qp, ROWS, INNER, QDIM, SCALE);
    gemm_mma<<<gProj, 256, GSM_BYTES>>>(ctx, Wk, nullptr, kp, ROWS, INNER, CDIM, 1.0f);
    gemm_mma<<<gProj, 256, GSM_BYTES>>>(ctx, Wv, nullptr, vp, ROWS, INNER, CDIM, 1.0f);

    attn_mma<<<dim3(NQ / 128, HEADS, BATCH), 256>>>();

    // out = attn_out @ Wo^T + bo
    gemm_mma<<<dim3(QDIM / 128, ROWS / 128), 256, GSM_BYTES>>>(ap, Wo, bo, out,
                                                               ROWS, QDIM, INNER, 1.0f);
}

// round 13
// speedup vs baseline: 1.3062x; 1.0191x over previous
#include <cuda_runtime.h>
#include <cstdint>
#include <cstddef>

#define HEADS    8
#define DIM_HEAD 64
#define QDIM     512
#define CDIM     768
#define INNER    512
#define BATCH    4
#define NQ       2048
#define NKV      2048
#define ROWS     (BATCH * NQ)   // 8192
#define SCALE    0.125f         // 64^-0.5

// Scratch (allocation-free rule: device globals)
__device__ float g_q[ROWS * INNER];
__device__ float g_k[ROWS * INNER];   // stored PAIR-PERMUTED within 8-col groups
__device__ float g_v[ROWS * INNER];
__device__ float g_ao[ROWS * INNER];

// ===========================================================================
// Warp-MMA tf32 helpers
// ===========================================================================
__device__ __forceinline__ uint32_t tf32_bits(float x) {
    uint32_t r;
    asm("cvt.rna.tf32.f32 %0, %1;" : "=r"(r) : "f"(x));
    return r;
}

__device__ __forceinline__ void tf32_split(float x, uint32_t& hi, uint32_t& lo) {
    hi = tf32_bits(x);
    lo = tf32_bits(x - __uint_as_float(hi));
}

__device__ __forceinline__ void split4(const float4& v, uint4& h, uint4& l) {
    tf32_split(v.x, h.x, l.x); tf32_split(v.y, h.y, l.y);
    tf32_split(v.z, h.z, l.z); tf32_split(v.w, h.w, l.w);
}

__device__ __forceinline__ uint4 hi4(const float4& v) {
    uint4 h;
    h.x = tf32_bits(v.x); h.y = tf32_bits(v.y);
    h.z = tf32_bits(v.z); h.w = tf32_bits(v.w);
    return h;
}

#define MMA_TF32(d, a, b)                                                     \
    asm volatile(                                                             \
        "mma.sync.aligned.m16n8k8.row.col.f32.tf32.tf32.f32 "                 \
        "{%0,%1,%2,%3}, {%4,%5,%6,%7}, {%8,%9}, {%0,%1,%2,%3};"               \
        : "+f"((d)[0]), "+f"((d)[1]), "+f"((d)[2]), "+f"((d)[3])              \
        : "r"((a)[0]), "r"((a)[1]), "r"((a)[2]), "r"((a)[3]),                 \
          "r"((b)[0]), "r"((b)[1]))

// cp.async helpers (LDGSTS, baseline sm_80+ PTX)
#define CP_ASYNC16(dst_u32, src_ptr)                                          \
    asm volatile("cp.async.cg.shared.global [%0], [%1], 16;"                  \
                 :: "r"(dst_u32), "l"(src_ptr))
#define CP_COMMIT()  asm volatile("cp.async.commit_group;" ::: "memory")
#define CP_WAIT1()   asm volatile("cp.async.wait_group 1;" ::: "memory")

// pair-permutation within 8-col groups: c -> pos so that (t, t+4) are adjacent
__device__ __forceinline__ int kperm(int c) {
    return (c & ~7) | (((c & 3) << 1) | ((c & 7) >> 2));
}

// ===========================================================================
// 2xTF32 NT GEMM, double-buffered + pipelined (round-12 mainloop, kept).
// C = scale*(A @ B^T) + bias, computed as A_hi @ (B_hi + B_lo)^T.
// permuteOut=1: output columns pair-permuted within 8-groups (for g_k).
// ===========================================================================
#define GBUF_UINTS 7680    // 3 * 128*20
#define GSM_BYTES  (2 * GBUF_UINTS * 4)

__global__ __launch_bounds__(256)
void gemm_mma(const float* __restrict__ A, const float* __restrict__ Bw,
              const float* __restrict__ bias, float* __restrict__ C,
              int M, int ldc, int K, float scale, int permuteOut)
{
    extern __shared__ uint32_t gsm[];

    const int tid    = threadIdx.x;
    const int warp   = tid >> 5;
    const int lane   = tid & 31;
    const int gid    = lane >> 2;
    const int tig    = lane & 3;
    const int warp_m = warp & 1;
    const int warp_n = warp >> 1;
    const int mBase  = blockIdx.y << 7;
    const int nBase  = blockIdx.x << 7;

    const int lrow = tid >> 2;          // 0..63
    const int lk4  = (tid & 3) << 2;    // 0,4,8,12

    const float* Ar0 = A  + (size_t)(mBase + lrow)      * K + lk4;
    const float* Ar1 = A  + (size_t)(mBase + lrow + 64) * K + lk4;
    const float* Br0 = Bw + (size_t)(nBase + lrow)      * K + lk4;
    const float* Br1 = Bw + (size_t)(nBase + lrow + 64) * K + lk4;

    float acc[4][4][4] = {};
    float4 pa0, pa1, pb0, pb1;

    // prologue: stage chunk 0
    pa0 = *(const float4*)Ar0; pa1 = *(const float4*)Ar1;
    pb0 = *(const float4*)Br0; pb1 = *(const float4*)Br1;
    {
        uint32_t* Ah = gsm;
        uint32_t* Bh = Ah + 2560;
        uint32_t* Bl = Bh + 2560;
        uint4 h, l;
        *(uint4*)&Ah[lrow * 20 + lk4]        = hi4(pa0);
        *(uint4*)&Ah[(lrow + 64) * 20 + lk4] = hi4(pa1);
        split4(pb0, h, l); *(uint4*)&Bh[lrow * 20 + lk4] = h; *(uint4*)&Bl[lrow * 20 + lk4] = l;
        split4(pb1, h, l); *(uint4*)&Bh[(lrow + 64) * 20 + lk4] = h; *(uint4*)&Bl[(lrow + 64) * 20 + lk4] = l;
    }

    const int nC = K >> 4;
    int p = 0;

    for (int c = 0; c < nC; c++) {
        __syncthreads();

        if (c + 1 < nC) {                 // prefetch next chunk (LDG early)
            const int k0 = (c + 1) << 4;
            pa0 = *(const float4*)(Ar0 + k0); pa1 = *(const float4*)(Ar1 + k0);
            pb0 = *(const float4*)(Br0 + k0); pb1 = *(const float4*)(Br1 + k0);
        }

        const uint32_t* Ah = gsm + p * GBUF_UINTS;
        const uint32_t* Bh = Ah + 2560;
        const uint32_t* Bl = Bh + 2560;

#pragma unroll
        for (int ks = 0; ks < 16; ks += 8) {
            uint32_t bh[4][2], bl[4][2];
#pragma unroll
            for (int ni = 0; ni < 4; ni++) {
                const int col = warp_n * 32 + ni * 8 + gid;
                bh[ni][0] = Bh[col * 20 + ks + tig];     bl[ni][0] = Bl[col * 20 + ks + tig];
                bh[ni][1] = Bh[col * 20 + ks + tig + 4]; bl[ni][1] = Bl[col * 20 + ks + tig + 4];
            }
#pragma unroll
            for (int mi = 0; mi < 4; mi++) {
                const int row = warp_m * 64 + mi * 16 + gid;
                uint32_t ah[4];
                ah[0] = Ah[row * 20 + ks + tig];
                ah[1] = Ah[(row + 8) * 20 + ks + tig];
                ah[2] = Ah[row * 20 + ks + tig + 4];
                ah[3] = Ah[(row + 8) * 20 + ks + tig + 4];
#pragma unroll
                for (int ni = 0; ni < 4; ni++) {
                    MMA_TF32(acc[mi][ni], ah, bh[ni]);
                    MMA_TF32(acc[mi][ni], ah, bl[ni]);
                }
            }
        }

        if (c + 1 < nC) {                 // store prefetched into other buffer
            uint32_t* Ah2 = gsm + (p ^ 1) * GBUF_UINTS;
            uint32_t* Bh2 = Ah2 + 2560;
            uint32_t* Bl2 = Bh2 + 2560;
            uint4 h, l;
            *(uint4*)&Ah2[lrow * 20 + lk4]        = hi4(pa0);
            *(uint4*)&Ah2[(lrow + 64) * 20 + lk4] = hi4(pa1);
            split4(pb0, h, l); *(uint4*)&Bh2[lrow * 20 + lk4] = h; *(uint4*)&Bl2[lrow * 20 + lk4] = l;
            split4(pb1, h, l); *(uint4*)&Bh2[(lrow + 64) * 20 + lk4] = h; *(uint4*)&Bl2[(lrow + 64) * 20 + lk4] = l;
        }
        p ^= 1;
    }

#pragma unroll
    for (int mi = 0; mi < 4; mi++) {
        const int row0 = mBase + warp_m * 64 + mi * 16 + gid;
#pragma unroll
        for (int ni = 0; ni < 4; ni++) {
            const int col = nBase + warp_n * 32 + ni * 8 + tig * 2;
            float b0 = 0.f, b1 = 0.f;
            if (bias) { b0 = bias[col]; b1 = bias[col + 1]; }
            float2 o0, o1;
            o0.x = acc[mi][ni][0] * scale + b0;
            o0.y = acc[mi][ni][1] * scale + b1;
            o1.x = acc[mi][ni][2] * scale + b0;
            o1.y = acc[mi][ni][3] * scale + b1;
            if (!permuteOut) {
                *(float2*)&C[(size_t)row0 * ldc + col]       = o0;
                *(float2*)&C[(size_t)(row0 + 8) * ldc + col] = o1;
            } else {
                const int p0 = kperm(col), p1 = kperm(col + 1);
                C[(size_t)row0 * ldc + p0]       = o0.x;
                C[(size_t)row0 * ldc + p1]       = o0.y;
                C[(size_t)(row0 + 8) * ldc + p0] = o1.x;
                C[(size_t)(row0 + 8) * ldc + p1] = o1.y;
            }
        }
    }
}

// ===========================================================================
// Tensor-core flash attention v4: cp.async double-buffered K/V.
// CTA = (b, h, 128 q-rows), 256 threads = 8 warps; warp owns 16 q-rows.
// KV tiles of 64, 2-deep cp.async group pipeline (zero register staging).
//  - g_k pre-permuted in gmem -> cp.async chunks are identity copies; S
//    B-frags remain LDS.64 pairs at [key][kc*8 + 2t].
//  - V row-major [key][d] stride 72.
//  - P: C-frag -> A-frag via lane shuffles (no smem).
//  - No cvt: tensor core reads top 19 bits of fp32 (truncation).
// Dynamic smem: 2 x (Ks 64*72 + Vs 64*72) uints = 73728 bytes.
// ===========================================================================
#define ABUF_UINTS 9216      // Ks 4608 + Vs 4608
#define ASM_BYTES  (2 * ABUF_UINTS * 4)

__global__ __launch_bounds__(256, 2)
void attn_mma()
{
    extern __shared__ uint32_t su[];

    const int tid  = threadIdx.x;
    const int warp = tid >> 5;
    const int lane = tid & 31;
    const int g    = lane >> 2;     // 0..7
    const int t    = lane & 3;      // 0..3
    const int qb   = blockIdx.x << 7;
    const int h    = blockIdx.y;
    const int b    = blockIdx.z;

    const uint32_t sbase = (uint32_t)__cvta_generic_to_shared(su);

    // Q fragments (raw fp32 bits; Q pre-scaled by SCALE)
    uint32_t qf[8][4];
    {
        const float* Qb = g_q + (size_t)(b * NQ + qb + warp * 16) * INNER + h * 64;
#pragma unroll
        for (int kc = 0; kc < 8; kc++) {
            qf[kc][0] = __float_as_uint(Qb[(size_t)g       * INNER + kc * 8 + t]);
            qf[kc][1] = __float_as_uint(Qb[(size_t)(g + 8) * INNER + kc * 8 + t]);
            qf[kc][2] = __float_as_uint(Qb[(size_t)g       * INNER + kc * 8 + t + 4]);
            qf[kc][3] = __float_as_uint(Qb[(size_t)(g + 8) * INNER + kc * 8 + t + 4]);
        }
    }

    const float* Kg0 = g_k + (size_t)(b * NKV) * INNER + h * 64;
    const float* Vg0 = g_v + (size_t)(b * NKV) * INNER + h * 64;

    // per-thread chunk coords: 4 x 16B for K, 4 x 16B for V
    const int r0 = tid >> 4;                 // 0..15 (+16 per i)
    const int c4 = (tid & 15) << 2;          // 0..60

    float m0 = -1e30f, m1 = -1e30f, l0 = 0.f, l1 = 0.f;
    float o[8][4] = {};

    const int shsrc0 = (g << 2) + (t >> 1);   // P source lane for cols t
    const int shsrc1 = shsrc0 + 2;            // P source lane for cols t+4
    const bool todd  = (t & 1);

    // ---- issue one tile's cp.async (8 x 16B per thread) into buffer p ----
#define ISSUE_TILE(kb_, p_)                                                   \
    do {                                                                      \
        const float* Kg_ = Kg0 + (size_t)(kb_) * INNER;                       \
        const float* Vg_ = Vg0 + (size_t)(kb_) * INNER;                       \
        _Pragma("unroll")                                                     \
        for (int i_ = 0; i_ < 4; i_++) {                                      \
            const int r_ = r0 + (i_ << 4);                                    \
            const uint32_t db_ = sbase + ((p_) * ABUF_UINTS + r_ * 72 + c4) * 4; \
            CP_ASYNC16(db_,        Kg_ + (size_t)r_ * INNER + c4);            \
            CP_ASYNC16(db_ + 4608 * 4, Vg_ + (size_t)r_ * INNER + c4);        \
        }                                                                     \
    } while (0)

    // prologue: stage tiles 0 and 1
    ISSUE_TILE(0, 0);  CP_COMMIT();
    ISSUE_TILE(64, 1); CP_COMMIT();

    for (int kb = 0; kb < NKV; kb += 64) {
        const int p = (kb >> 6) & 1;
        CP_WAIT1();          // this tile's copies done (<=1 group pending)
        __syncthreads();     // all threads' copies visible

        const uint32_t* Ks = su + p * ABUF_UINTS;
        const uint32_t* Vs = Ks + 4608;

        // ---- S = Q @ K^T  (16 x 64 per warp), paired LDS.64 B-frags ----
        float sf[8][4];
#pragma unroll
        for (int ni = 0; ni < 8; ni++)
#pragma unroll
            for (int r = 0; r < 4; r++) sf[ni][r] = 0.f;

#pragma unroll
        for (int kc = 0; kc < 8; kc++) {
#pragma unroll
            for (int ni = 0; ni < 8; ni++) {
                uint2 bp = *(const uint2*)&Ks[(ni * 8 + g) * 72 + kc * 8 + t * 2];
                uint32_t bb[2] = {bp.x, bp.y};
                MMA_TF32(sf[ni], qf[kc], bb);
            }
        }

        // ---- online softmax (rows g and g+8) ----
        float tm0 = -1e30f, tm1 = -1e30f;
#pragma unroll
        for (int ni = 0; ni < 8; ni++) {
            tm0 = fmaxf(tm0, fmaxf(sf[ni][0], sf[ni][1]));
            tm1 = fmaxf(tm1, fmaxf(sf[ni][2], sf[ni][3]));
        }
        tm0 = fmaxf(tm0, __shfl_xor_sync(0xFFFFFFFF, tm0, 1));
        tm0 = fmaxf(tm0, __shfl_xor_sync(0xFFFFFFFF, tm0, 2));
        tm1 = fmaxf(tm1, __shfl_xor_sync(0xFFFFFFFF, tm1, 1));
        tm1 = fmaxf(tm1, __shfl_xor_sync(0xFFFFFFFF, tm1, 2));

        float mn0 = fmaxf(m0, tm0), mn1 = fmaxf(m1, tm1);
        float a0 = __expf(m0 - mn0), a1 = __expf(m1 - mn1);
        m0 = mn0; m1 = mn1;

        float ps0 = 0.f, ps1 = 0.f;
#pragma unroll
        for (int ni = 0; ni < 8; ni++) {
            sf[ni][0] = __expf(sf[ni][0] - m0); ps0 += sf[ni][0];
            sf[ni][1] = __expf(sf[ni][1] - m0); ps0 += sf[ni][1];
            sf[ni][2] = __expf(sf[ni][2] - m1); ps1 += sf[ni][2];
            sf[ni][3] = __expf(sf[ni][3] - m1); ps1 += sf[ni][3];
        }
        ps0 += __shfl_xor_sync(0xFFFFFFFF, ps0, 1);
        ps0 += __shfl_xor_sync(0xFFFFFFFF, ps0, 2);
        ps1 += __shfl_xor_sync(0xFFFFFFFF, ps1, 1);
        ps1 += __shfl_xor_sync(0xFFFFFFFF, ps1, 2);
        l0 = l0 * a0 + ps0;
        l1 = l1 * a1 + ps1;

#pragma unroll
        for (int s = 0; s < 8; s++) {
            o[s][0] *= a0; o[s][1] *= a0;
            o[s][2] *= a1; o[s][3] *= a1;
        }

        // ---- O += P @ V : A-frag of P via shuffles (raw fp32 bits) ----
#pragma unroll
        for (int kc = 0; kc < 8; kc++) {
            float f0  = __shfl_sync(0xFFFFFFFF, sf[kc][0], shsrc0);
            float f1  = __shfl_sync(0xFFFFFFFF, sf[kc][1], shsrc0);
            float f2  = __shfl_sync(0xFFFFFFFF, sf[kc][2], shsrc0);
            float f3  = __shfl_sync(0xFFFFFFFF, sf[kc][3], shsrc0);
            float f0b = __shfl_sync(0xFFFFFFFF, sf[kc][0], shsrc1);
            float f1b = __shfl_sync(0xFFFFFFFF, sf[kc][1], shsrc1);
            float f2b = __shfl_sync(0xFFFFFFFF, sf[kc][2], shsrc1);
            float f3b = __shfl_sync(0xFFFFFFFF, sf[kc][3], shsrc1);
            uint32_t pa[4];
            pa[0] = __float_as_uint(todd ? f1  : f0);
            pa[1] = __float_as_uint(todd ? f3  : f2);
            pa[2] = __float_as_uint(todd ? f1b : f0b);
            pa[3] = __float_as_uint(todd ? f3b : f2b);
#pragma unroll
            for (int s = 0; s < 8; s++) {
                uint32_t bb[2];
                bb[0] = Vs[(kc * 8 + t) * 72 + s * 8 + g];
                bb[1] = Vs[(kc * 8 + t + 4) * 72 + s * 8 + g];
                MMA_TF32(o[s], pa, bb);
            }
        }

        __syncthreads();     // all warps done reading buffer p
        if (kb + 128 < NKV)
            ISSUE_TILE(kb + 128, p);   // refill buffer p for tile i+2
        CP_COMMIT();                    // commit (possibly empty) group
    }

    // ---- normalize and write out ----
    const float inv0 = 1.f / l0, inv1 = 1.f / l1;
    const int row0 = b * NQ + qb + warp * 16 + g;
#pragma unroll
    for (int s = 0; s < 8; s++) {
        const int col = h * 64 + s * 8 + t * 2;
        float2 w0, w1;
        w0.x = o[s][0] * inv0; w0.y = o[s][1] * inv0;
        w1.x = o[s][2] * inv1; w1.y = o[s][3] * inv1;
        *(float2*)&g_ao[(size_t)row0 * INNER + col]       = w0;
        *(float2*)&g_ao[(size_t)(row0 + 8) * INNER + col] = w1;
    }
#undef ISSUE_TILE
}

// ---------------------------------------------------------------------------
extern "C" void kernel_launch(void* const* d_in, const int* in_sizes, int n_in,
                              void* d_out, int out_size)
{
    const float* x   = (const float*)d_in[0];  // [4,2048,512]
    const float* ctx = (const float*)d_in[1];  // [4,2048,768]
    const float* Wq  = (const float*)d_in[2];  // [512,512]
    const float* Wk  = (const float*)d_in[3];  // [512,768]
    const float* Wv  = (const float*)d_in[4];  // [512,768]
    const float* Wo  = (const float*)d_in[5];  // [512,512]
    const float* bo  = (const float*)d_in[6];  // [512]
    float* out = (float*)d_out;

    float *qp, *kp, *vp, *ap;
    cudaGetSymbolAddress((void**)&qp, g_q);
    cudaGetSymbolAddress((void**)&kp, g_k);
    cudaGetSymbolAddress((void**)&vp, g_v);
    cudaGetSymbolAddress((void**)&ap, g_ao);

    cudaFuncSetAttribute(gemm_mma, cudaFuncAttributeMaxDynamicSharedMemorySize,
                         GSM_BYTES);
    cudaFuncSetAttribute(attn_mma, cudaFuncAttributeMaxDynamicSharedMemorySize,
                         ASM_BYTES);

    dim3 gProj(INNER / 128, ROWS / 128);   // (4, 64)

    // Q = x @ Wq^T * SCALE ; K = ctx @ Wk^T (pair-permuted) ; V = ctx @ Wv^T
    gemm_mma<<<gProj, 256, GSM_BYTES>>>(x,   Wq, nullptr, qp, ROWS, INNER, QDIM, SCALE, 0);
    gemm_mma<<<gProj, 256, GSM_BYTES>>>(ctx, Wk, nullptr, kp, ROWS, INNER, CDIM, 1.0f, 1);
    gemm_mma<<<gProj, 256, GSM_BYTES>>>(ctx, Wv, nullptr, vp, ROWS, INNER, CDIM, 1.0f, 0);

    attn_mma<<<dim3(NQ / 128, HEADS, BATCH), 256, ASM_BYTES>>>();

    // out = attn_out @ Wo^T + bo
    gemm_mma<<<dim3(QDIM / 128, ROWS / 128), 256, GSM_BYTES>>>(ap, Wo, bo, out,
                                                               ROWS, QDIM, INNER, 1.0f, 0);
}

// round 17
// speedup vs baseline: 1.6149x; 1.2363x over previous
#include <cuda_runtime.h>
#include <cuda_fp16.h>
#include <cstdint>
#include <cstddef>

#define HEADS    8
#define DIM_HEAD 64
#define QDIM     512
#define CDIM     768
#define INNER    512
#define BATCH    4
#define NQ       2048
#define NKV      2048
#define ROWS     (BATCH * NQ)   // 8192
#define SCALE    0.125f         // 64^-0.5

// Scratch (allocation-free rule: device globals)
__device__ float  g_q  [ROWS * INNER];
__device__ __half g_k16[ROWS * INNER];   // fp16 K, plain row-major
__device__ __half g_v16[ROWS * INNER];   // fp16 V, plain row-major
__device__ float  g_ao [ROWS * INNER];

// ===========================================================================
// helpers
// ===========================================================================
__device__ __forceinline__ uint32_t tf32_bits(float x) {
    uint32_t r;
    asm("cvt.rna.tf32.f32 %0, %1;" : "=r"(r) : "f"(x));
    return r;
}

__device__ __forceinline__ void tf32_split(float x, uint32_t& hi, uint32_t& lo) {
    hi = tf32_bits(x);
    lo = tf32_bits(x - __uint_as_float(hi));
}

__device__ __forceinline__ void split4(const float4& v, uint4& h, uint4& l) {
    tf32_split(v.x, h.x, l.x); tf32_split(v.y, h.y, l.y);
    tf32_split(v.z, h.z, l.z); tf32_split(v.w, h.w, l.w);
}

__device__ __forceinline__ uint4 hi4(const float4& v) {
    uint4 h;
    h.x = tf32_bits(v.x); h.y = tf32_bits(v.y);
    h.z = tf32_bits(v.z); h.w = tf32_bits(v.w);
    return h;
}

__device__ __forceinline__ uint32_t f2h2(float lo, float hi) {
    __half2 h = __floats2half2_rn(lo, hi);
    return *(uint32_t*)&h;
}

#define MMA_TF32(d, a, b)                                                     \
    asm volatile(                                                             \
        "mma.sync.aligned.m16n8k8.row.col.f32.tf32.tf32.f32 "                 \
        "{%0,%1,%2,%3}, {%4,%5,%6,%7}, {%8,%9}, {%0,%1,%2,%3};"               \
        : "+f"((d)[0]), "+f"((d)[1]), "+f"((d)[2]), "+f"((d)[3])              \
        : "r"((a)[0]), "r"((a)[1]), "r"((a)[2]), "r"((a)[3]),                 \
          "r"((b)[0]), "r"((b)[1]))

#define MMA_F16(d, a, b)                                                      \
    asm volatile(                                                             \
        "mma.sync.aligned.m16n8k16.row.col.f32.f16.f16.f32 "                  \
        "{%0,%1,%2,%3}, {%4,%5,%6,%7}, {%8,%9}, {%0,%1,%2,%3};"               \
        : "+f"((d)[0]), "+f"((d)[1]), "+f"((d)[2]), "+f"((d)[3])              \
        : "r"((a)[0]), "r"((a)[1]), "r"((a)[2]), "r"((a)[3]),                 \
          "r"((b)[0]), "r"((b)[1]))

#define LDSM_X2(r0, r1, a)                                                    \
    asm volatile("ldmatrix.sync.aligned.m8n8.x2.shared.b16 {%0,%1}, [%2];"    \
                 : "=r"(r0), "=r"(r1) : "r"(a))
#define LDSM_X2T(r0, r1, a)                                                   \
    asm volatile("ldmatrix.sync.aligned.m8n8.x2.trans.shared.b16 {%0,%1}, [%2];" \
                 : "=r"(r0), "=r"(r1) : "r"(a))

#define CP_ASYNC16(dst_u32, src_ptr)                                          \
    asm volatile("cp.async.cg.shared.global [%0], [%1], 16;"                  \
                 :: "r"(dst_u32), "l"(src_ptr))
#define CP_COMMIT()  asm volatile("cp.async.commit_group;" ::: "memory")
#define CP_WAIT1()   asm volatile("cp.async.wait_group 1;" ::: "memory")

// ===========================================================================
// 2xTF32 NT GEMM, double-buffered + pipelined (round-12 mainloop, kept).
// C = scale*(A @ B^T) + bias as A_hi @ (B_hi + B_lo)^T.
// C16 != null -> write fp16 output (plain row-major, half2 stores).
// ===========================================================================
#define GBUF_UINTS 7680    // 3 * 128*20
#define GSM_BYTES  (2 * GBUF_UINTS * 4)

__global__ __launch_bounds__(256)
void gemm_mma(const float* __restrict__ A, const float* __restrict__ Bw,
              const float* __restrict__ bias, float* __restrict__ C,
              __half* __restrict__ C16,
              int M, int ldc, int K, float scale)
{
    extern __shared__ uint32_t gsm[];

    const int tid    = threadIdx.x;
    const int warp   = tid >> 5;
    const int lane   = tid & 31;
    const int gid    = lane >> 2;
    const int tig    = lane & 3;
    const int warp_m = warp & 1;
    const int warp_n = warp >> 1;
    const int mBase  = blockIdx.y << 7;
    const int nBase  = blockIdx.x << 7;

    const int lrow = tid >> 2;          // 0..63
    const int lk4  = (tid & 3) << 2;    // 0,4,8,12

    const float* Ar0 = A  + (size_t)(mBase + lrow)      * K + lk4;
    const float* Ar1 = A  + (size_t)(mBase + lrow + 64) * K + lk4;
    const float* Br0 = Bw + (size_t)(nBase + lrow)      * K + lk4;
    const float* Br1 = Bw + (size_t)(nBase + lrow + 64) * K + lk4;

    float acc[4][4][4] = {};
    float4 pa0, pa1, pb0, pb1;

    pa0 = *(const float4*)Ar0; pa1 = *(const float4*)Ar1;
    pb0 = *(const float4*)Br0; pb1 = *(const float4*)Br1;
    {
        uint32_t* Ah = gsm;
        uint32_t* Bh = Ah + 2560;
        uint32_t* Bl = Bh + 2560;
        uint4 h, l;
        *(uint4*)&Ah[lrow * 20 + lk4]        = hi4(pa0);
        *(uint4*)&Ah[(lrow + 64) * 20 + lk4] = hi4(pa1);
        split4(pb0, h, l); *(uint4*)&Bh[lrow * 20 + lk4] = h; *(uint4*)&Bl[lrow * 20 + lk4] = l;
        split4(pb1, h, l); *(uint4*)&Bh[(lrow + 64) * 20 + lk4] = h; *(uint4*)&Bl[(lrow + 64) * 20 + lk4] = l;
    }

    const int nC = K >> 4;
    int p = 0;

    for (int c = 0; c < nC; c++) {
        __syncthreads();

        if (c + 1 < nC) {
            const int k0 = (c + 1) << 4;
            pa0 = *(const float4*)(Ar0 + k0); pa1 = *(const float4*)(Ar1 + k0);
            pb0 = *(const float4*)(Br0 + k0); pb1 = *(const float4*)(Br1 + k0);
        }

        const uint32_t* Ah = gsm + p * GBUF_UINTS;
        const uint32_t* Bh = Ah + 2560;
        const uint32_t* Bl = Bh + 2560;

#pragma unroll
        for (int ks = 0; ks < 16; ks += 8) {
            uint32_t bh[4][2], bl[4][2];
#pragma unroll
            for (int ni = 0; ni < 4; ni++) {
                const int col = warp_n * 32 + ni * 8 + gid;
                bh[ni][0] = Bh[col * 20 + ks + tig];     bl[ni][0] = Bl[col * 20 + ks + tig];
                bh[ni][1] = Bh[col * 20 + ks + tig + 4]; bl[ni][1] = Bl[col * 20 + ks + tig + 4];
            }
#pragma unroll
            for (int mi = 0; mi < 4; mi++) {
                const int row = warp_m * 64 + mi * 16 + gid;
                uint32_t ah[4];
                ah[0] = Ah[row * 20 + ks + tig];
                ah[1] = Ah[(row + 8) * 20 + ks + tig];
                ah[2] = Ah[row * 20 + ks + tig + 4];
                ah[3] = Ah[(row + 8) * 20 + ks + tig + 4];
#pragma unroll
                for (int ni = 0; ni < 4; ni++) {
                    MMA_TF32(acc[mi][ni], ah, bh[ni]);
                    MMA_TF32(acc[mi][ni], ah, bl[ni]);
                }
            }
        }

        if (c + 1 < nC) {
            uint32_t* Ah2 = gsm + (p ^ 1) * GBUF_UINTS;
            uint32_t* Bh2 = Ah2 + 2560;
            uint32_t* Bl2 = Bh2 + 2560;
            uint4 h, l;
            *(uint4*)&Ah2[lrow * 20 + lk4]        = hi4(pa0);
            *(uint4*)&Ah2[(lrow + 64) * 20 + lk4] = hi4(pa1);
            split4(pb0, h, l); *(uint4*)&Bh2[lrow * 20 + lk4] = h; *(uint4*)&Bl2[lrow * 20 + lk4] = l;
            split4(pb1, h, l); *(uint4*)&Bh2[(lrow + 64) * 20 + lk4] = h; *(uint4*)&Bl2[(lrow + 64) * 20 + lk4] = l;
        }
        p ^= 1;
    }

#pragma unroll
    for (int mi = 0; mi < 4; mi++) {
        const int row0 = mBase + warp_m * 64 + mi * 16 + gid;
#pragma unroll
        for (int ni = 0; ni < 4; ni++) {
            const int col = nBase + warp_n * 32 + ni * 8 + tig * 2;
            float b0 = 0.f, b1 = 0.f;
            if (bias) { b0 = bias[col]; b1 = bias[col + 1]; }
            float2 o0, o1;
            o0.x = acc[mi][ni][0] * scale + b0;
            o0.y = acc[mi][ni][1] * scale + b1;
            o1.x = acc[mi][ni][2] * scale + b0;
            o1.y = acc[mi][ni][3] * scale + b1;
            if (!C16) {
                *(float2*)&C[(size_t)row0 * ldc + col]       = o0;
                *(float2*)&C[(size_t)(row0 + 8) * ldc + col] = o1;
            } else {
                *(__half2*)&C16[(size_t)row0 * ldc + col]       = __floats2half2_rn(o0.x, o0.y);
                *(__half2*)&C16[(size_t)(row0 + 8) * ldc + col] = __floats2half2_rn(o1.x, o1.y);
            }
        }
    }
}

// ===========================================================================
// fp16 tensor-core flash attention v5 (m16n8k16 + ldmatrix + cp.async).
// CTA = (b, h, 128 q-rows), 256 threads = 8 warps; warp owns 16 q-rows.
// KV tiles of 64, cp.async double-buffered (2-deep group pipeline).
//  - K/V fp16 plain row-major in smem, row stride 144B (conflict-free).
//  - S B-frags: ldmatrix.x2 (no trans) on K rows.
//  - PV B-frags: ldmatrix.x2.trans on V rows.
//  - S C-frag == PV A-frag layout: P needs only cvt.f16x2 packs, no shuffles.
// smem: 2 x (K 64*144 + V 64*144) = 36864 bytes (static).
// ===========================================================================
#define KVROW_B 144
#define KBUF_B  (64 * KVROW_B)    // 9216
#define BUF_B   (2 * KBUF_B)      // 18432 (K + V)

__global__ __launch_bounds__(256, 2)
void attn_mma()
{
    __shared__ __align__(16) char sm[2 * BUF_B];

    const int tid  = threadIdx.x;
    const int warp = tid >> 5;
    const int lane = tid & 31;
    const int g    = lane >> 2;     // 0..7
    const int t    = lane & 3;      // 0..3
    const int qb   = blockIdx.x << 7;
    const int h    = blockIdx.y;
    const int b    = blockIdx.z;

    const uint32_t sbase = (uint32_t)__cvta_generic_to_shared(sm);

    // Q fragments fp16 (m16n8k16 A layout), from fp32 g_q (pre-scaled)
    uint32_t qf[4][4];
    {
        const float* Qb = g_q + (size_t)(b * NQ + qb + warp * 16) * INNER + h * 64;
        const float* q0 = Qb + (size_t)g * INNER;
        const float* q1 = Qb + (size_t)(g + 8) * INNER;
#pragma unroll
        for (int kc = 0; kc < 4; kc++) {
            const int d0 = kc * 16 + 2 * t;
            qf[kc][0] = f2h2(q0[d0],     q0[d0 + 1]);
            qf[kc][1] = f2h2(q1[d0],     q1[d0 + 1]);
            qf[kc][2] = f2h2(q0[d0 + 8], q0[d0 + 9]);
            qf[kc][3] = f2h2(q1[d0 + 8], q1[d0 + 9]);
        }
    }

    const __half* Kg0 = g_k16 + (size_t)(b * NKV) * INNER + h * 64;
    const __half* Vg0 = g_v16 + (size_t)(b * NKV) * INNER + h * 64;

    // cp.async coords: 512 chunks of 16B per operand, 2 per thread each
    const int crow = tid >> 3;          // 0..31 (+32 second iter)
    const int ccol = tid & 7;           // 0..7  (16B chunk within 128B row)

    // ldmatrix per-lane row offsets
    const uint32_t krow_off = (uint32_t)((lane & 7) * KVROW_B + ((lane & 8) ? 16 : 0));
    const uint32_t vrow_off = (uint32_t)((lane & 15) * KVROW_B);

    float m0 = -1e30f, m1 = -1e30f, l0 = 0.f, l1 = 0.f;
    float o[8][4] = {};

#define ISSUE_TILE(kb_, p_)                                                   \
    do {                                                                      \
        const __half* Kg_ = Kg0 + (size_t)(kb_) * INNER;                      \
        const __half* Vg_ = Vg0 + (size_t)(kb_) * INNER;                      \
        _Pragma("unroll")                                                     \
        for (int i_ = 0; i_ < 2; i_++) {                                      \
            const int r_ = crow + (i_ << 5);                                  \
            const uint32_t db_ = sbase + (p_) * BUF_B + r_ * KVROW_B + ccol * 16; \
            CP_ASYNC16(db_,          Kg_ + (size_t)r_ * INNER + ccol * 8);    \
            CP_ASYNC16(db_ + KBUF_B, Vg_ + (size_t)r_ * INNER + ccol * 8);    \
        }                                                                     \
    } while (0)

    ISSUE_TILE(0, 0);  CP_COMMIT();
    ISSUE_TILE(64, 1); CP_COMMIT();

    for (int kb = 0; kb < NKV; kb += 64) {
        const int p = (kb >> 6) & 1;
        CP_WAIT1();
        __syncthreads();

        const uint32_t kb_base = sbase + p * BUF_B;
        const uint32_t vb_base = kb_base + KBUF_B;

        // ---- S = Q @ K^T : 4 kc x 8 ni m16n8k16 MMAs ----
        float sf[8][4];
#pragma unroll
        for (int ni = 0; ni < 8; ni++)
#pragma unroll
            for (int r = 0; r < 4; r++) sf[ni][r] = 0.f;

#pragma unroll
        for (int kc = 0; kc < 4; kc++) {
#pragma unroll
            for (int ni = 0; ni < 8; ni++) {
                uint32_t bb[2];
                LDSM_X2(bb[0], bb[1],
                        kb_base + (uint32_t)(ni * 8 * KVROW_B + kc * 32) + krow_off);
                MMA_F16(sf[ni], qf[kc], bb);
            }
        }

        // ---- online softmax (rows g and g+8) ----
        float tm0 = -1e30f, tm1 = -1e30f;
#pragma unroll
        for (int ni = 0; ni < 8; ni++) {
            tm0 = fmaxf(tm0, fmaxf(sf[ni][0], sf[ni][1]));
            tm1 = fmaxf(tm1, fmaxf(sf[ni][2], sf[ni][3]));
        }
        tm0 = fmaxf(tm0, __shfl_xor_sync(0xFFFFFFFF, tm0, 1));
        tm0 = fmaxf(tm0, __shfl_xor_sync(0xFFFFFFFF, tm0, 2));
        tm1 = fmaxf(tm1, __shfl_xor_sync(0xFFFFFFFF, tm1, 1));
        tm1 = fmaxf(tm1, __shfl_xor_sync(0xFFFFFFFF, tm1, 2));

        float mn0 = fmaxf(m0, tm0), mn1 = fmaxf(m1, tm1);
        float a0 = __expf(m0 - mn0), a1 = __expf(m1 - mn1);
        m0 = mn0; m1 = mn1;

        float ps0 = 0.f, ps1 = 0.f;
#pragma unroll
        for (int ni = 0; ni < 8; ni++) {
            sf[ni][0] = __expf(sf[ni][0] - m0); ps0 += sf[ni][0];
            sf[ni][1] = __expf(sf[ni][1] - m0); ps0 += sf[ni][1];
            sf[ni][2] = __expf(sf[ni][2] - m1); ps1 += sf[ni][2];
            sf[ni][3] = __expf(sf[ni][3] - m1); ps1 += sf[ni][3];
        }
        ps0 += __shfl_xor_sync(0xFFFFFFFF, ps0, 1);
        ps0 += __shfl_xor_sync(0xFFFFFFFF, ps0, 2);
        ps1 += __shfl_xor_sync(0xFFFFFFFF, ps1, 1);
        ps1 += __shfl_xor_sync(0xFFFFFFFF, ps1, 2);
        l0 = l0 * a0 + ps0;
        l1 = l1 * a1 + ps1;

#pragma unroll
        for (int s = 0; s < 8; s++) {
            o[s][0] *= a0; o[s][1] *= a0;
            o[s][2] *= a1; o[s][3] *= a1;
        }

        // ---- O += P @ V : P C-frag == A-frag (pack only), V via ldmatrix.trans ----
#pragma unroll
        for (int kc = 0; kc < 4; kc++) {
            uint32_t pa[4];
            pa[0] = f2h2(sf[2 * kc][0],     sf[2 * kc][1]);
            pa[1] = f2h2(sf[2 * kc][2],     sf[2 * kc][3]);
            pa[2] = f2h2(sf[2 * kc + 1][0], sf[2 * kc + 1][1]);
            pa[3] = f2h2(sf[2 * kc + 1][2], sf[2 * kc + 1][3]);
#pragma unroll
            for (int s = 0; s < 8; s++) {
                uint32_t bb[2];
                LDSM_X2T(bb[0], bb[1],
                         vb_base + (uint32_t)(kc * 16 * KVROW_B + s * 16) + vrow_off);
                MMA_F16(o[s], pa, bb);
            }
        }

        __syncthreads();
        if (kb + 128 < NKV)
            ISSUE_TILE(kb + 128, p);
        CP_COMMIT();
    }

    // ---- normalize and write out ----
    const float inv0 = 1.f / l0, inv1 = 1.f / l1;
    const int row0 = b * NQ + qb + warp * 16 + g;
#pragma unroll
    for (int s = 0; s < 8; s++) {
        const int col = h * 64 + s * 8 + t * 2;
        float2 w0, w1;
        w0.x = o[s][0] * inv0; w0.y = o[s][1] * inv0;
        w1.x = o[s][2] * inv1; w1.y = o[s][3] * inv1;
        *(float2*)&g_ao[(size_t)row0 * INNER + col]       = w0;
        *(float2*)&g_ao[(size_t)(row0 + 8) * INNER + col] = w1;
    }
#undef ISSUE_TILE
}

// ---------------------------------------------------------------------------
extern "C" void kernel_launch(void* const* d_in, const int* in_sizes, int n_in,
                              void* d_out, int out_size)
{
    const float* x   = (const float*)d_in[0];  // [4,2048,512]
    const float* ctx = (const float*)d_in[1];  // [4,2048,768]
    const float* Wq  = (const float*)d_in[2];  // [512,512]
    const float* Wk  = (const float*)d_in[3];  // [512,768]
    const float* Wv  = (const float*)d_in[4];  // [512,768]
    const float* Wo  = (const float*)d_in[5];  // [512,512]
    const float* bo  = (const float*)d_in[6];  // [512]
    float* out = (float*)d_out;

    float *qp, *ap;
    __half *kp16, *vp16;
    cudaGetSymbolAddress((void**)&qp,   g_q);
    cudaGetSymbolAddress((void**)&kp16, g_k16);
    cudaGetSymbolAddress((void**)&vp16, g_v16);
    cudaGetSymbolAddress((void**)&ap,   g_ao);

    cudaFuncSetAttribute(gemm_mma, cudaFuncAttributeMaxDynamicSharedMemorySize,
                         GSM_BYTES);

    dim3 gProj(INNER / 128, ROWS / 128);   // (4, 64)

    // Q = x @ Wq^T * SCALE (fp32) ; K,V = ctx @ W^T (fp16 out)
    gemm_mma<<<gProj, 256, GSM_BYTES>>>(x,   Wq, nullptr, qp, nullptr,
                                        ROWS, INNER, QDIM, SCALE);
    gemm_mma<<<gProj, 256, GSM_BYTES>>>(ctx, Wk, nullptr, nullptr, kp16,
                                        ROWS, INNER, CDIM, 1.0f);
    gemm_mma<<<gProj, 256, GSM_BYTES>>>(ctx, Wv, nullptr, nullptr, vp16,
                                        ROWS, INNER, CDIM, 1.0f);

    attn_mma<<<dim3(NQ / 128, HEADS, BATCH), 256>>>();

    // out = attn_out @ Wo^T + bo (fp32)
    gemm_mma<<<dim3(QDIM / 128, ROWS / 128), 256, GSM_BYTES>>>(ap, Wo, bo, out, nullptr,
                                                               ROWS, QDIM, INNER, 1.0f);
}